// round 1
// baseline (speedup 1.0000x reference)
#include <cuda_runtime.h>
#include <cstdint>
#include <math.h>

// ---------------------------------------------------------------------------
// Problem constants
// ---------------------------------------------------------------------------
#define NS 10000
#define NW 30000
#define ND 200
#define DIN 768
#define HC 256          // conv1: H=4,C=64 ; conv2: H=1,C=256 -> per-node payload always 256
#define PROJ_H 128
#define EMAX 200000

// ---------------------------------------------------------------------------
// Scratch (device globals; no allocation allowed)
// ---------------------------------------------------------------------------
__device__ float g_h_sent[NS * DIN];
__device__ float g_h_word[NW * DIN];
__device__ float g_h_doc [ND * DIN];
__device__ float g_feat  [NW * HC];      // per-type transformed source features (max 30000 rows)
__device__ float g_vs    [DIN * 4];
__device__ float g_vd    [DIN * 4];
__device__ float g_als   [NW * 4];
__device__ float g_ald   [NW * 4];
__device__ float g_m     [NW * 4];
__device__ float g_den   [NW * 4];
__device__ float g_e     [EMAX * 4];
__device__ float g_ex    [EMAX * 4];
__device__ float g_s1    [NS * HC];
__device__ float g_w1    [NW * HC];
__device__ float g_d1    [ND * HC];
__device__ float g_s2    [NS * HC];
__device__ float g_ptmp  [NS * PROJ_H];

// ---------------------------------------------------------------------------
// GEMM: C[M,N] = act(A[M,K] @ B[K,N] + bias)
// 64x64 tile, BK=16, 256 threads, 4x4 per thread
// ---------------------------------------------------------------------------
#define BM 64
#define BN 64
#define BK 16

__global__ void gemm_kernel(const float* __restrict__ A, const float* __restrict__ B,
                            const float* __restrict__ bias, float* __restrict__ C,
                            int M, int N, int K, int relu)
{
    __shared__ float As[BK][BM];
    __shared__ float Bs[BK][BN];
    int tid = threadIdx.x;
    int tx = tid & 15, ty = tid >> 4;
    int row0 = blockIdx.y * BM;
    int col0 = blockIdx.x * BN;
    float acc[4][4] = {};

    for (int k0 = 0; k0 < K; k0 += BK) {
#pragma unroll
        for (int i = 0; i < 4; i++) {
            int idx = tid + i * 256;            // 0..1023
            int m = idx >> 4, kk = idx & 15;    // A tile: 64 x 16
            float v = 0.f;
            int gm = row0 + m;
            if (gm < M) v = A[(size_t)gm * K + k0 + kk];
            As[kk][m] = v;
        }
#pragma unroll
        for (int i = 0; i < 4; i++) {
            int idx = tid + i * 256;
            int kk = idx >> 6, n = idx & 63;    // B tile: 16 x 64
            float v = 0.f;
            int gn = col0 + n;
            if (gn < N) v = B[(size_t)(k0 + kk) * N + gn];
            Bs[kk][n] = v;
        }
        __syncthreads();
#pragma unroll
        for (int kk = 0; kk < BK; kk++) {
            float a[4], b[4];
#pragma unroll
            for (int i = 0; i < 4; i++) a[i] = As[kk][ty * 4 + i];
#pragma unroll
            for (int j = 0; j < 4; j++) b[j] = Bs[kk][tx * 4 + j];
#pragma unroll
            for (int i = 0; i < 4; i++)
#pragma unroll
                for (int j = 0; j < 4; j++)
                    acc[i][j] += a[i] * b[j];
        }
        __syncthreads();
    }

#pragma unroll
    for (int i = 0; i < 4; i++) {
        int m = row0 + ty * 4 + i;
        if (m >= M) continue;
#pragma unroll
        for (int j = 0; j < 4; j++) {
            int n = col0 + tx * 4 + j;
            if (n >= N) continue;
            float v = acc[i][j] + (bias ? bias[n] : 0.f);
            if (relu) v = fmaxf(v, 0.f);
            C[(size_t)m * N + n] = v;
        }
    }
}

// ---------------------------------------------------------------------------
// build V[k,h] = sum_c W[k, h*C + c] * a[h*C + c]
// ---------------------------------------------------------------------------
__global__ void build_v_kernel(const float* __restrict__ W, const float* __restrict__ a,
                               float* __restrict__ V, int K, int H, int C)
{
    int idx = blockIdx.x * blockDim.x + threadIdx.x;
    if (idx >= K * H) return;
    int k = idx / H, h = idx % H;
    const float* w = W + (size_t)k * H * C + h * C;
    const float* av = a + h * C;
    float s = 0.f;
    for (int c = 0; c < C; c++) s += w[c] * av[c];
    V[idx] = s;
}

// ---------------------------------------------------------------------------
// out[n,h] = sum_k X[n,k] * V[k,h]   (H<=4), one warp per row
// ---------------------------------------------------------------------------
__global__ void gemv_att_kernel(const float* __restrict__ X, const float* __restrict__ V,
                                float* __restrict__ out, int N, int K, int H)
{
    int warp = (blockIdx.x * blockDim.x + threadIdx.x) >> 5;
    int lane = threadIdx.x & 31;
    if (warp >= N) return;
    const float* x = X + (size_t)warp * K;
    float s0 = 0.f, s1 = 0.f, s2 = 0.f, s3 = 0.f;
    for (int k = lane; k < K; k += 32) {
        float xv = x[k];
        const float* v = V + k * H;
        s0 += xv * v[0];
        if (H > 1) { s1 += xv * v[1]; s2 += xv * v[2]; s3 += xv * v[3]; }
    }
#pragma unroll
    for (int o = 16; o > 0; o >>= 1) {
        s0 += __shfl_xor_sync(0xffffffffu, s0, o);
        s1 += __shfl_xor_sync(0xffffffffu, s1, o);
        s2 += __shfl_xor_sync(0xffffffffu, s2, o);
        s3 += __shfl_xor_sync(0xffffffffu, s3, o);
    }
    if (lane == 0) {
        out[warp * H + 0] = s0;
        if (H > 1) {
            out[warp * H + 1] = s1;
            out[warp * H + 2] = s2;
            out[warp * H + 3] = s3;
        }
    }
}

// ---------------------------------------------------------------------------
// misc small kernels
// ---------------------------------------------------------------------------
__global__ void fill_kernel(float* __restrict__ p, float v, int n)
{
    int i = blockIdx.x * blockDim.x + threadIdx.x;
    for (; i < n; i += gridDim.x * blockDim.x) p[i] = v;
}

__global__ void add_bias_rows_kernel(float* __restrict__ out, const float* __restrict__ b, int total)
{
    int i = blockIdx.x * blockDim.x + threadIdx.x;
    for (; i < total; i += gridDim.x * blockDim.x) out[i] += b[i & (HC - 1)];
}

__device__ __forceinline__ void atomicMaxFloat(float* addr, float val)
{
    if (val >= 0.f) atomicMax((int*)addr, __float_as_int(val));
    else            atomicMin((unsigned int*)addr, __float_as_uint(val));
}

// pass1: e = leakyrelu(als[src]+ald[dst]); store; segment max
__global__ void edge_pass1_kernel(const int* __restrict__ src, const int* __restrict__ dst,
                                  const float* __restrict__ als, const float* __restrict__ ald,
                                  float* __restrict__ ebuf, float* __restrict__ m, int E, int H)
{
    int idx = blockIdx.x * blockDim.x + threadIdx.x;
    if (idx >= E * H) return;
    int e = idx / H, h = idx - e * H;
    int s = src[e], d = dst[e];
    float v = als[s * H + h] + ald[d * H + h];
    v = (v > 0.f) ? v : 0.2f * v;
    ebuf[idx] = v;
    atomicMaxFloat(&m[d * H + h], v);
}

// pass2: ex = exp(e - m[dst]); store; segment sum
__global__ void edge_pass2_kernel(const int* __restrict__ dst,
                                  const float* __restrict__ ebuf, const float* __restrict__ m,
                                  float* __restrict__ exbuf, float* __restrict__ den, int E, int H)
{
    int idx = blockIdx.x * blockDim.x + threadIdx.x;
    if (idx >= E * H) return;
    int e = idx / H, h = idx - e * H;
    int d = dst[e];
    float ex = __expf(ebuf[idx] - m[d * H + h]);
    exbuf[idx] = ex;
    atomicAdd(&den[d * H + h], ex);
}

// pass3: out[dst] += feat[src] * alpha ; one warp per edge, 256 floats per edge
__global__ void edge_scatter_kernel(const int* __restrict__ src, const int* __restrict__ dst,
                                    const float* __restrict__ exbuf, const float* __restrict__ den,
                                    const float* __restrict__ feat, float* __restrict__ out,
                                    int E, int H, int C)
{
    int e = (blockIdx.x * blockDim.x + threadIdx.x) >> 5;
    if (e >= E) return;
    int lane = threadIdx.x & 31;
    int s = src[e], d = dst[e];
    const float4* fs = (const float4*)(feat + (size_t)s * HC);
    float* od = out + (size_t)d * HC;
#pragma unroll
    for (int j = 0; j < 2; j++) {
        int i4 = lane + j * 32;        // float4 index 0..63
        int base = i4 * 4;
        int h = base / C;              // uniform within a float4 (C is 64 or 256)
        float alpha = exbuf[e * H + h] / (den[d * H + h] + 1e-16f);
        float4 v = fs[i4];
        atomicAdd(&od[base + 0], v.x * alpha);
        atomicAdd(&od[base + 1], v.y * alpha);
        atomicAdd(&od[base + 2], v.z * alpha);
        atomicAdd(&od[base + 3], v.w * alpha);
    }
}

// (optional relu) + LayerNorm over last dim (D=256), one block per row
__global__ void relu_ln_kernel(const float* __restrict__ in, float* __restrict__ out, int pre_relu)
{
    int n = blockIdx.x;
    int t = threadIdx.x;
    float v = in[(size_t)n * HC + t];
    if (pre_relu) v = fmaxf(v, 0.f);
    __shared__ float red[HC];
    red[t] = v;
    __syncthreads();
#pragma unroll
    for (int s = HC / 2; s > 0; s >>= 1) {
        if (t < s) red[t] += red[t + s];
        __syncthreads();
    }
    float mu = red[0] * (1.f / HC);
    __syncthreads();
    float dv = v - mu;
    red[t] = dv * dv;
    __syncthreads();
#pragma unroll
    for (int s = HC / 2; s > 0; s >>= 1) {
        if (t < s) red[t] += red[t + s];
        __syncthreads();
    }
    float var = red[0] * (1.f / HC);
    out[(size_t)n * HC + t] = dv * rsqrtf(var + 1e-5f);
}

// ---------------------------------------------------------------------------
// host orchestration
// ---------------------------------------------------------------------------
static inline void launch_gemm(const float* A, const float* B, const float* bias, float* C,
                               int M, int N, int K, int relu)
{
    dim3 grid((N + BN - 1) / BN, (M + BM - 1) / BM);
    gemm_kernel<<<grid, 256>>>(A, B, bias, C, M, N, K, relu);
}

static inline void launch_fill(float* p, float v, int n)
{
    int blocks = (n + 255) / 256;
    if (blocks > 8192) blocks = 8192;
    fill_kernel<<<blocks, 256>>>(p, v, n);
}

extern "C" void kernel_launch(void* const* d_in, const int* in_sizes, int n_in,
                              void* d_out, int out_size)
{
    const float* x_sent = (const float*)d_in[0];
    const float* x_word = (const float*)d_in[1];
    const float* x_doc  = (const float*)d_in[2];
    const int*   ei[6]  = { (const int*)d_in[3], (const int*)d_in[4], (const int*)d_in[5],
                            (const int*)d_in[6], (const int*)d_in[7], (const int*)d_in[8] };
    int          Ecnt[6];
    for (int t = 0; t < 6; t++) Ecnt[t] = in_sizes[3 + t] / 2;
    const float* Wls = (const float*)d_in[9];
    const float* bls = (const float*)d_in[10];
    const float* Wlw = (const float*)d_in[11];
    const float* blw = (const float*)d_in[12];
    const float* Wld = (const float*)d_in[13];
    const float* bld = (const float*)d_in[14];
    const float* W1s = (const float*)d_in[15];
    const float* W1d = (const float*)d_in[16];
    const float* a1s = (const float*)d_in[17];
    const float* a1d = (const float*)d_in[18];
    const float* b1  = (const float*)d_in[19];
    const float* W2s = (const float*)d_in[20];
    const float* W2d = (const float*)d_in[21];
    const float* a2s = (const float*)d_in[22];
    const float* a2d = (const float*)d_in[23];
    const float* b2  = (const float*)d_in[24];
    const float* Wp1 = (const float*)d_in[25];
    const float* bp1 = (const float*)d_in[26];
    const float* Wp2 = (const float*)d_in[27];
    const float* bp2 = (const float*)d_in[28];

    float *h_sent, *h_word, *h_doc, *feat, *vs, *vd, *als, *ald, *m, *den, *ebuf, *exbuf;
    float *s1, *w1, *d1, *s2, *ptmp;
    cudaGetSymbolAddress((void**)&h_sent, g_h_sent);
    cudaGetSymbolAddress((void**)&h_word, g_h_word);
    cudaGetSymbolAddress((void**)&h_doc,  g_h_doc);
    cudaGetSymbolAddress((void**)&feat,   g_feat);
    cudaGetSymbolAddress((void**)&vs,     g_vs);
    cudaGetSymbolAddress((void**)&vd,     g_vd);
    cudaGetSymbolAddress((void**)&als,    g_als);
    cudaGetSymbolAddress((void**)&ald,    g_ald);
    cudaGetSymbolAddress((void**)&m,      g_m);
    cudaGetSymbolAddress((void**)&den,    g_den);
    cudaGetSymbolAddress((void**)&ebuf,   g_e);
    cudaGetSymbolAddress((void**)&exbuf,  g_ex);
    cudaGetSymbolAddress((void**)&s1,     g_s1);
    cudaGetSymbolAddress((void**)&w1,     g_w1);
    cudaGetSymbolAddress((void**)&d1,     g_d1);
    cudaGetSymbolAddress((void**)&s2,     g_s2);
    cudaGetSymbolAddress((void**)&ptmp,   g_ptmp);

    float* out_s2  = (float*)d_out;
    float* out_prj = out_s2 + (size_t)NS * HC;

    // ---- stage A: input linears + relu ----
    launch_gemm(x_sent, Wls, bls, h_sent, NS, DIN, DIN, 1);
    launch_gemm(x_word, Wlw, blw, h_word, NW, DIN, DIN, 1);
    launch_gemm(x_doc,  Wld, bld, h_doc,  ND, DIN, DIN, 1);

    // ---- conv1: 6 edge types, H=4, C=64 ----
    launch_fill(s1, 0.f, NS * HC);
    launch_fill(w1, 0.f, NW * HC);
    launch_fill(d1, 0.f, ND * HC);

    const float* srcX1[6] = { h_sent, h_sent, h_word, h_sent, h_doc, h_sent };
    int          Nsrc1[6] = { NS, NS, NW, NS, ND, NS };
    const float* dstX1[6] = { h_sent, h_sent, h_sent, h_word, h_sent, h_doc };
    int          Ndst1[6] = { NS, NS, NS, NW, NS, ND };
    float*       acc1[6]  = { s1, s1, s1, w1, s1, d1 };

    const int H1 = 4, C1 = 64;
    for (int t = 0; t < 6; t++) {
        int E = Ecnt[t], Nsr = Nsrc1[t], Ndt = Ndst1[t];
        const int* esrc = ei[t];
        const int* edst = ei[t] + E;

        build_v_kernel<<<(DIN * H1 + 127) / 128, 128>>>(W1s + (size_t)t * DIN * HC, a1s + t * HC, vs, DIN, H1, C1);
        build_v_kernel<<<(DIN * H1 + 127) / 128, 128>>>(W1d + (size_t)t * DIN * HC, a1d + t * HC, vd, DIN, H1, C1);
        launch_gemm(srcX1[t], W1s + (size_t)t * DIN * HC, nullptr, feat, Nsr, HC, DIN, 0);
        gemv_att_kernel<<<(Nsr * 32 + 127) / 128, 128>>>(srcX1[t], vs, als, Nsr, DIN, H1);
        gemv_att_kernel<<<(Ndt * 32 + 127) / 128, 128>>>(dstX1[t], vd, ald, Ndt, DIN, H1);
        launch_fill(m,   -INFINITY, Ndt * H1);
        launch_fill(den, 0.f,       Ndt * H1);
        edge_pass1_kernel<<<(E * H1 + 255) / 256, 256>>>(esrc, edst, als, ald, ebuf, m, E, H1);
        edge_pass2_kernel<<<(E * H1 + 255) / 256, 256>>>(edst, ebuf, m, exbuf, den, E, H1);
        edge_scatter_kernel<<<(E * 32 + 255) / 256, 256>>>(esrc, edst, exbuf, den, feat, acc1[t], E, H1, C1);
        add_bias_rows_kernel<<<(Ndt * HC + 255) / 256 > 8192 ? 8192 : (Ndt * HC + 255) / 256, 256>>>(acc1[t], b1 + t * HC, Ndt * HC);
    }

    // ---- relu + LN ----
    relu_ln_kernel<<<NS, HC>>>(s1, s1, 1);
    relu_ln_kernel<<<NW, HC>>>(w1, w1, 1);
    relu_ln_kernel<<<ND, HC>>>(d1, d1, 1);

    // ---- conv2: types {0,1,2,4} into sentences, H=1, C=256 ----
    launch_fill(s2, 0.f, NS * HC);

    const int    t2[4]    = { 0, 1, 2, 4 };
    const float* srcX2[4] = { s1, s1, w1, d1 };
    int          Nsrc2[4] = { NS, NS, NW, ND };
    const int H2 = 1, C2 = 256;
    for (int i = 0; i < 4; i++) {
        int t = t2[i];
        int E = Ecnt[t], Nsr = Nsrc2[i];
        const int* esrc = ei[t];
        const int* edst = ei[t] + E;

        build_v_kernel<<<(HC * H2 + 127) / 128, 128>>>(W2s + (size_t)t * HC * HC, a2s + t * HC, vs, HC, H2, C2);
        build_v_kernel<<<(HC * H2 + 127) / 128, 128>>>(W2d + (size_t)t * HC * HC, a2d + t * HC, vd, HC, H2, C2);
        launch_gemm(srcX2[i], W2s + (size_t)t * HC * HC, nullptr, feat, Nsr, HC, HC, 0);
        gemv_att_kernel<<<(Nsr * 32 + 127) / 128, 128>>>(srcX2[i], vs, als, Nsr, HC, H2);
        gemv_att_kernel<<<(NS * 32 + 127) / 128, 128>>>(s1, vd, ald, NS, HC, H2);
        launch_fill(m,   -INFINITY, NS * H2);
        launch_fill(den, 0.f,       NS * H2);
        edge_pass1_kernel<<<(E * H2 + 255) / 256, 256>>>(esrc, edst, als, ald, ebuf, m, E, H2);
        edge_pass2_kernel<<<(E * H2 + 255) / 256, 256>>>(edst, ebuf, m, exbuf, den, E, H2);
        edge_scatter_kernel<<<(E * 32 + 255) / 256, 256>>>(esrc, edst, exbuf, den, feat, s2, E, H2, C2);
        add_bias_rows_kernel<<<(NS * HC + 255) / 256, 256>>>(s2, b2 + t * HC, NS * HC);
    }

    // ---- final LN (no relu) -> output s2 ----
    relu_ln_kernel<<<NS, HC>>>(s2, out_s2, 0);

    // ---- projection head ----
    if (out_size >= NS * (HC + PROJ_H)) {
        launch_gemm(out_s2, Wp1, bp1, ptmp, NS, PROJ_H, HC, 1);
        launch_gemm(ptmp, Wp2, bp2, out_prj, NS, PROJ_H, PROJ_H, 0);
    }
}

// round 2
// speedup vs baseline: 1.3755x; 1.3755x over previous
#include <cuda_runtime.h>
#include <cstdint>
#include <math.h>

// ---------------------------------------------------------------------------
// Problem constants
// ---------------------------------------------------------------------------
#define NS 10000
#define NW 30000
#define ND 200
#define DIN 768
#define HC 256
#define PROJ_H 128
#define AS (NW * 4)          // attention-value stride per slot
#define VS (DIN * 4)         // V vector stride per slot
#define FEAT_ROWS 70200
#define EH_MAX 2600000

// ---------------------------------------------------------------------------
// Scratch (device globals; no allocation allowed)
// ---------------------------------------------------------------------------
__device__ float g_h_sent[NS * DIN];
__device__ float g_h_word[NW * DIN];
__device__ float g_h_doc [ND * DIN];
__device__ float g_feat  [FEAT_ROWS * HC];
__device__ float g_V     [6 * VS];
__device__ float g_als   [6 * AS];
__device__ float g_ald   [6 * AS];
__device__ float g_m     [6 * AS];
__device__ float g_den   [6 * AS];
__device__ float g_e     [EH_MAX];
__device__ float g_ex    [EH_MAX];
__device__ float g_s1    [NS * HC];
__device__ float g_w1    [NW * HC];
__device__ float g_d1    [ND * HC];
__device__ float g_s2    [NS * HC];
__device__ float g_ptmp  [NS * PROJ_H];

// ---------------------------------------------------------------------------
// metadata struct (passed by value)
// ---------------------------------------------------------------------------
struct ConvMeta {
    const int*   ei[6];      // stacked [2,E] edge arrays
    const float* dstX[6];    // dst-side node features (for ald gemv)
    float*       out[6];     // scatter accumulators
    int E[6];
    int cumEH[7];
    int cumE[7];
    int srcRows[6];
    int dstRows[6];
    int foff[6];             // feat row offsets
    int tmap[6];             // slot -> weight/type index
    int nt, H, C, K;
};

// ---------------------------------------------------------------------------
// SGEMM: C[M,N] = act(A[M,K] @ B[K,N] + bias)
// 128x128 tile, BK=16, 256 threads, 8x8 per thread, float4 everywhere.
// Requires: K % 16 == 0, N % 128 == 0 (true for all calls: N in {768,256,128})
// ---------------------------------------------------------------------------
#define GM 128
#define GN 128
#define GK 16

__global__ __launch_bounds__(256, 2)
void sgemm_kernel(const float* __restrict__ A, const float* __restrict__ B,
                  const float* __restrict__ bias, float* __restrict__ C,
                  int M, int N, int K, int relu)
{
    __shared__ float As[GK][GM];
    __shared__ float Bs[GK][GN];
    int tid = threadIdx.x;
    int row0 = blockIdx.y * GM;
    int col0 = blockIdx.x * GN;
    int tx = tid & 15, ty = tid >> 4;
    float acc[8][8] = {};

    const float* Aptr = A + (size_t)row0 * K;
    const float* Bptr = B + col0;

    // load index precompute
    int a_r[2], a_c[2], b_k[2], b_n[2];
#pragma unroll
    for (int i = 0; i < 2; i++) {
        int idx = tid + i * 256;
        a_r[i] = idx >> 2;          // 0..127
        a_c[i] = (idx & 3) * 4;     // 0,4,8,12
        b_k[i] = idx >> 5;          // 0..15
        b_n[i] = (idx & 31) * 4;    // 0..124
    }

    for (int k0 = 0; k0 < K; k0 += GK) {
#pragma unroll
        for (int i = 0; i < 2; i++) {
            float4 v = make_float4(0.f, 0.f, 0.f, 0.f);
            if (row0 + a_r[i] < M)
                v = *(const float4*)(Aptr + (size_t)a_r[i] * K + k0 + a_c[i]);
            As[a_c[i] + 0][a_r[i]] = v.x;
            As[a_c[i] + 1][a_r[i]] = v.y;
            As[a_c[i] + 2][a_r[i]] = v.z;
            As[a_c[i] + 3][a_r[i]] = v.w;
        }
#pragma unroll
        for (int i = 0; i < 2; i++) {
            float4 v = *(const float4*)(Bptr + (size_t)(k0 + b_k[i]) * N + b_n[i]);
            *(float4*)&Bs[b_k[i]][b_n[i]] = v;
        }
        __syncthreads();
#pragma unroll
        for (int kk = 0; kk < GK; kk++) {
            float a[8], b[8];
            *(float4*)&a[0] = *(const float4*)&As[kk][ty * 8];
            *(float4*)&a[4] = *(const float4*)&As[kk][ty * 8 + 4];
            *(float4*)&b[0] = *(const float4*)&Bs[kk][tx * 8];
            *(float4*)&b[4] = *(const float4*)&Bs[kk][tx * 8 + 4];
#pragma unroll
            for (int i = 0; i < 8; i++)
#pragma unroll
                for (int j = 0; j < 8; j++)
                    acc[i][j] += a[i] * b[j];
        }
        __syncthreads();
    }

    // epilogue
    float bv[8];
#pragma unroll
    for (int j = 0; j < 8; j++) bv[j] = bias ? bias[col0 + tx * 8 + j] : 0.f;
#pragma unroll
    for (int i = 0; i < 8; i++) {
        int m = row0 + ty * 8 + i;
        if (m >= M) continue;
        float* crow = C + (size_t)m * N + col0 + tx * 8;
        float4 o0, o1;
        float vv[8];
#pragma unroll
        for (int j = 0; j < 8; j++) {
            float v = acc[i][j] + bv[j];
            if (relu) v = fmaxf(v, 0.f);
            vv[j] = v;
        }
        o0 = make_float4(vv[0], vv[1], vv[2], vv[3]);
        o1 = make_float4(vv[4], vv[5], vv[6], vv[7]);
        *(float4*)(crow + 0) = o0;
        *(float4*)(crow + 4) = o1;
    }
}

// ---------------------------------------------------------------------------
// build dst-side attention vectors V[slot][k][h] = sum_c Wd[t,k,h*C+c]*ad[t,h,c]
// ---------------------------------------------------------------------------
__global__ void build_vd_all(const float* __restrict__ Wd, const float* __restrict__ ad,
                             float* __restrict__ Vall, int K, int H, int C, ConvMeta md)
{
    int slot = blockIdx.y;
    int typ = md.tmap[slot];
    int idx = blockIdx.x * blockDim.x + threadIdx.x;
    if (idx >= K * H) return;
    int k = idx / H, h = idx - (idx / H) * H;
    const float* w = Wd + (size_t)typ * K * HC + (size_t)k * HC + h * C;
    const float* av = ad + typ * HC + h * C;
    float s = 0.f;
    for (int c = 0; c < C; c++) s += w[c] * av[c];
    Vall[slot * VS + k * H + h] = s;
}

// ---------------------------------------------------------------------------
// als[slot][row][h] = sum_c feat[foff+row, h*C+c] * a_s[t, h*C+c]  (warp per (row,h))
// ---------------------------------------------------------------------------
__global__ void als_feat_all(const float* __restrict__ feat, const float* __restrict__ a_s,
                             float* __restrict__ als_all, ConvMeta md)
{
    int slot = blockIdx.y;
    int id = (blockIdx.x * blockDim.x + threadIdx.x) >> 5;
    int lane = threadIdx.x & 31;
    int H = md.H, C = md.C;
    int rows = md.srcRows[slot];
    if (id >= rows * H) return;
    int row = id / H, h = id - (id / H) * H;
    const float* f = feat + (size_t)(md.foff[slot] + row) * HC + h * C;
    const float* a = a_s + md.tmap[slot] * HC + h * C;
    float s = 0.f;
    for (int c = lane; c < C; c += 32) s += f[c] * a[c];
#pragma unroll
    for (int o = 16; o > 0; o >>= 1) s += __shfl_xor_sync(0xffffffffu, s, o);
    if (lane == 0) als_all[slot * AS + row * H + h] = s;
}

// ---------------------------------------------------------------------------
// ald[slot][row][h] = X[row] . V[slot][:,h]     (warp per row, H<=4)
// ---------------------------------------------------------------------------
__global__ void gemv_ald_all(const float* __restrict__ Vall, float* __restrict__ ald_all,
                             ConvMeta md)
{
    int slot = blockIdx.y;
    int warp = (blockIdx.x * blockDim.x + threadIdx.x) >> 5;
    int lane = threadIdx.x & 31;
    int rows = md.dstRows[slot];
    if (warp >= rows) return;
    int K = md.K, H = md.H;
    const float* x = md.dstX[slot] + (size_t)warp * K;
    const float* V = Vall + slot * VS;
    float s0 = 0.f, s1 = 0.f, s2 = 0.f, s3 = 0.f;
    for (int k = lane; k < K; k += 32) {
        float xv = x[k];
        const float* v = V + k * H;
        s0 += xv * v[0];
        if (H > 1) { s1 += xv * v[1]; s2 += xv * v[2]; s3 += xv * v[3]; }
    }
#pragma unroll
    for (int o = 16; o > 0; o >>= 1) {
        s0 += __shfl_xor_sync(0xffffffffu, s0, o);
        s1 += __shfl_xor_sync(0xffffffffu, s1, o);
        s2 += __shfl_xor_sync(0xffffffffu, s2, o);
        s3 += __shfl_xor_sync(0xffffffffu, s3, o);
    }
    if (lane == 0) {
        float* o = ald_all + slot * AS + warp * H;
        o[0] = s0;
        if (H > 1) { o[1] = s1; o[2] = s2; o[3] = s3; }
    }
}

// ---------------------------------------------------------------------------
// misc
// ---------------------------------------------------------------------------
__global__ void fill_md_kernel(float* __restrict__ m, float* __restrict__ den, int n)
{
    int i = blockIdx.x * blockDim.x + threadIdx.x;
    for (; i < n; i += gridDim.x * blockDim.x) { m[i] = -INFINITY; den[i] = 0.f; }
}

__global__ void init_bias_kernel(float* __restrict__ out, const float* __restrict__ b,
                                 int4 ts, int total)
{
    int i = blockIdx.x * blockDim.x + threadIdx.x;
    for (; i < total; i += gridDim.x * blockDim.x) {
        int c = i & (HC - 1);
        float v = b[ts.x * HC + c];
        if (ts.y >= 0) v += b[ts.y * HC + c];
        if (ts.z >= 0) v += b[ts.z * HC + c];
        if (ts.w >= 0) v += b[ts.w * HC + c];
        out[i] = v;
    }
}

__device__ __forceinline__ void atomicMaxFloat(float* addr, float val)
{
    if (val >= 0.f) atomicMax((int*)addr, __float_as_int(val));
    else            atomicMin((unsigned int*)addr, __float_as_uint(val));
}

// ---------------------------------------------------------------------------
// edge pipeline (batched over all slots)
// ---------------------------------------------------------------------------
__global__ void edge_pass1_all(const float* __restrict__ als_all, const float* __restrict__ ald_all,
                               float* __restrict__ ebuf, float* __restrict__ m_all, ConvMeta md)
{
    int idx = blockIdx.x * blockDim.x + threadIdx.x;
    if (idx >= md.cumEH[md.nt]) return;
    int slot = 0;
    while (idx >= md.cumEH[slot + 1]) slot++;
    int local = idx - md.cumEH[slot];
    int H = md.H;
    int e, h;
    if (H == 4) { e = local >> 2; h = local & 3; } else { e = local; h = 0; }
    const int* ei = md.ei[slot];
    int s = ei[e], d = ei[md.E[slot] + e];
    float v = als_all[slot * AS + s * H + h] + ald_all[slot * AS + d * H + h];
    v = (v > 0.f) ? v : 0.2f * v;
    ebuf[idx] = v;
    atomicMaxFloat(&m_all[slot * AS + d * H + h], v);
}

__global__ void edge_pass2_all(const float* __restrict__ ebuf, const float* __restrict__ m_all,
                               float* __restrict__ exbuf, float* __restrict__ den_all, ConvMeta md)
{
    int idx = blockIdx.x * blockDim.x + threadIdx.x;
    if (idx >= md.cumEH[md.nt]) return;
    int slot = 0;
    while (idx >= md.cumEH[slot + 1]) slot++;
    int local = idx - md.cumEH[slot];
    int H = md.H;
    int e, h;
    if (H == 4) { e = local >> 2; h = local & 3; } else { e = local; h = 0; }
    const int* ei = md.ei[slot];
    int d = ei[md.E[slot] + e];
    float ex = __expf(ebuf[idx] - m_all[slot * AS + d * H + h]);
    exbuf[idx] = ex;
    atomicAdd(&den_all[slot * AS + d * H + h], ex);
}

__global__ void edge_scatter_all(const float* __restrict__ exbuf, const float* __restrict__ den_all,
                                 const float* __restrict__ feat, ConvMeta md)
{
    int wf = (blockIdx.x * blockDim.x + threadIdx.x) >> 5;
    if (wf >= md.cumE[md.nt]) return;
    int lane = threadIdx.x & 31;
    int slot = 0;
    while (wf >= md.cumE[slot + 1]) slot++;
    int e = wf - md.cumE[slot];
    int H = md.H;
    const int* ei = md.ei[slot];
    int s = ei[e], d = ei[md.E[slot] + e];
    const float4* fs = (const float4*)(feat + (size_t)(md.foff[slot] + s) * HC);
    float* od = md.out[slot] + (size_t)d * HC;
    int ebase = md.cumEH[slot] + e * H;
    const float* dslot = den_all + slot * AS + d * H;
#pragma unroll
    for (int j = 0; j < 2; j++) {
        int i4 = lane + j * 32;
        int base = i4 * 4;
        int h = (H == 4) ? (base >> 6) : 0;
        float alpha = exbuf[ebase + h] / (dslot[h] + 1e-16f);
        float4 v = fs[i4];
        atomicAdd(&od[base + 0], v.x * alpha);
        atomicAdd(&od[base + 1], v.y * alpha);
        atomicAdd(&od[base + 2], v.z * alpha);
        atomicAdd(&od[base + 3], v.w * alpha);
    }
}

// ---------------------------------------------------------------------------
// (optional relu) + LayerNorm over last dim D=256, one 256-thread block per row
// ---------------------------------------------------------------------------
__global__ void relu_ln_kernel(const float* __restrict__ in, float* __restrict__ out, int pre_relu)
{
    int n = blockIdx.x;
    int t = threadIdx.x;
    int lane = t & 31, w = t >> 5;
    float v = in[(size_t)n * HC + t];
    if (pre_relu) v = fmaxf(v, 0.f);
    __shared__ float ws[8];
    float s = v;
#pragma unroll
    for (int o = 16; o > 0; o >>= 1) s += __shfl_xor_sync(0xffffffffu, s, o);
    if (lane == 0) ws[w] = s;
    __syncthreads();
    float mu = 0.f;
#pragma unroll
    for (int i = 0; i < 8; i++) mu += ws[i];
    mu *= (1.f / HC);
    __syncthreads();
    float dv = v - mu;
    s = dv * dv;
#pragma unroll
    for (int o = 16; o > 0; o >>= 1) s += __shfl_xor_sync(0xffffffffu, s, o);
    if (lane == 0) ws[w] = s;
    __syncthreads();
    float var = 0.f;
#pragma unroll
    for (int i = 0; i < 8; i++) var += ws[i];
    var *= (1.f / HC);
    out[(size_t)n * HC + t] = dv * rsqrtf(var + 1e-5f);
}

// ---------------------------------------------------------------------------
// host orchestration
// ---------------------------------------------------------------------------
static inline void launch_sgemm(const float* A, const float* B, const float* bias, float* C,
                                int M, int N, int K, int relu)
{
    dim3 grid(N / GN, (M + GM - 1) / GM);
    sgemm_kernel<<<grid, 256>>>(A, B, bias, C, M, N, K, relu);
}

extern "C" void kernel_launch(void* const* d_in, const int* in_sizes, int n_in,
                              void* d_out, int out_size)
{
    const float* x_sent = (const float*)d_in[0];
    const float* x_word = (const float*)d_in[1];
    const float* x_doc  = (const float*)d_in[2];
    const int*   ei[6]  = { (const int*)d_in[3], (const int*)d_in[4], (const int*)d_in[5],
                            (const int*)d_in[6], (const int*)d_in[7], (const int*)d_in[8] };
    int Ecnt[6];
    for (int t = 0; t < 6; t++) Ecnt[t] = in_sizes[3 + t] / 2;
    const float* Wls = (const float*)d_in[9];
    const float* bls = (const float*)d_in[10];
    const float* Wlw = (const float*)d_in[11];
    const float* blw = (const float*)d_in[12];
    const float* Wld = (const float*)d_in[13];
    const float* bld = (const float*)d_in[14];
    const float* W1s = (const float*)d_in[15];
    const float* W1d = (const float*)d_in[16];
    const float* a1s = (const float*)d_in[17];
    const float* a1d = (const float*)d_in[18];
    const float* b1  = (const float*)d_in[19];
    const float* W2s = (const float*)d_in[20];
    const float* W2d = (const float*)d_in[21];
    const float* a2s = (const float*)d_in[22];
    const float* a2d = (const float*)d_in[23];
    const float* b2  = (const float*)d_in[24];
    const float* Wp1 = (const float*)d_in[25];
    const float* bp1 = (const float*)d_in[26];
    const float* Wp2 = (const float*)d_in[27];
    const float* bp2 = (const float*)d_in[28];

    float *h_sent, *h_word, *h_doc, *feat, *Vall, *als, *ald, *m, *den, *ebuf, *exbuf;
    float *s1, *w1, *d1, *s2, *ptmp;
    cudaGetSymbolAddress((void**)&h_sent, g_h_sent);
    cudaGetSymbolAddress((void**)&h_word, g_h_word);
    cudaGetSymbolAddress((void**)&h_doc,  g_h_doc);
    cudaGetSymbolAddress((void**)&feat,   g_feat);
    cudaGetSymbolAddress((void**)&Vall,   g_V);
    cudaGetSymbolAddress((void**)&als,    g_als);
    cudaGetSymbolAddress((void**)&ald,    g_ald);
    cudaGetSymbolAddress((void**)&m,      g_m);
    cudaGetSymbolAddress((void**)&den,    g_den);
    cudaGetSymbolAddress((void**)&ebuf,   g_e);
    cudaGetSymbolAddress((void**)&exbuf,  g_ex);
    cudaGetSymbolAddress((void**)&s1,     g_s1);
    cudaGetSymbolAddress((void**)&w1,     g_w1);
    cudaGetSymbolAddress((void**)&d1,     g_d1);
    cudaGetSymbolAddress((void**)&s2,     g_s2);
    cudaGetSymbolAddress((void**)&ptmp,   g_ptmp);

    float* out_s2  = (float*)d_out;
    float* out_prj = out_s2 + (size_t)NS * HC;

    // ---- stage A: input linears + relu ----
    launch_sgemm(x_sent, Wls, bls, h_sent, NS, DIN, DIN, 1);
    launch_sgemm(x_word, Wlw, blw, h_word, NW, DIN, DIN, 1);
    launch_sgemm(x_doc,  Wld, bld, h_doc,  ND, DIN, DIN, 1);

    // ---- conv1 metadata ----
    ConvMeta m1 = {};
    {
        const float* srcX1[6] = { h_sent, h_sent, h_word, h_sent, h_doc, h_sent };
        int          Nsrc1[6] = { NS, NS, NW, NS, ND, NS };
        const float* dstX1[6] = { h_sent, h_sent, h_sent, h_word, h_sent, h_doc };
        int          Ndst1[6] = { NS, NS, NS, NW, NS, ND };
        float*       acc1[6]  = { s1, s1, s1, w1, s1, d1 };
        int fo = 0;
        m1.nt = 6; m1.H = 4; m1.C = 64; m1.K = DIN;
        m1.cumEH[0] = 0; m1.cumE[0] = 0;
        for (int t = 0; t < 6; t++) {
            m1.ei[t] = ei[t];
            m1.dstX[t] = dstX1[t];
            m1.out[t] = acc1[t];
            m1.E[t] = Ecnt[t];
            m1.cumEH[t + 1] = m1.cumEH[t] + Ecnt[t] * 4;
            m1.cumE[t + 1] = m1.cumE[t] + Ecnt[t];
            m1.srcRows[t] = Nsrc1[t];
            m1.dstRows[t] = Ndst1[t];
            m1.foff[t] = fo;
            m1.tmap[t] = t;
            fo += Nsrc1[t];
        }
        // feat GEMMs
        for (int t = 0; t < 6; t++)
            launch_sgemm(srcX1[t], W1s + (size_t)t * DIN * HC, nullptr,
                         feat + (size_t)m1.foff[t] * HC, Nsrc1[t], HC, DIN, 0);
    }

    // bias-preloaded accumulators
    init_bias_kernel<<<4096, 256>>>(s1, b1, make_int4(0, 1, 2, 4), NS * HC);
    init_bias_kernel<<<4096, 256>>>(w1, b1, make_int4(3, -1, -1, -1), NW * HC);
    init_bias_kernel<<<256,  256>>>(d1, b1, make_int4(5, -1, -1, -1), ND * HC);

    // attention values
    build_vd_all<<<dim3((DIN * 4 + 127) / 128, 6), 128>>>(W1d, a1d, Vall, DIN, 4, 64, m1);
    als_feat_all<<<dim3((NW * 4 + 7) / 8, 6), 256>>>(feat, a1s, als, m1);
    gemv_ald_all<<<dim3((NW + 7) / 8, 6), 256>>>(Vall, ald, m1);

    // edge softmax + scatter
    fill_md_kernel<<<2048, 256>>>(m, den, 6 * AS);
    {
        int tot = m1.cumEH[6];
        edge_pass1_all<<<(tot + 255) / 256, 256>>>(als, ald, ebuf, m, m1);
        edge_pass2_all<<<(tot + 255) / 256, 256>>>(ebuf, m, exbuf, den, m1);
        int totw = m1.cumE[6];
        edge_scatter_all<<<(totw * 32 + 255) / 256, 256>>>(exbuf, den, feat, m1);
    }

    // ---- relu + LN ----
    relu_ln_kernel<<<NS, HC>>>(s1, s1, 1);
    relu_ln_kernel<<<NW, HC>>>(w1, w1, 1);
    relu_ln_kernel<<<ND, HC>>>(d1, d1, 1);

    // ---- conv2 metadata (types {0,1,2,4} -> sentences) ----
    ConvMeta m2 = {};
    {
        const int    t2[4]    = { 0, 1, 2, 4 };
        const float* srcX2[4] = { s1, s1, w1, d1 };
        int          Nsrc2[4] = { NS, NS, NW, ND };
        int fo = 0;
        m2.nt = 4; m2.H = 1; m2.C = 256; m2.K = HC;
        m2.cumEH[0] = 0; m2.cumE[0] = 0;
        for (int i = 0; i < 4; i++) {
            int t = t2[i];
            m2.ei[i] = ei[t];
            m2.dstX[i] = s1;
            m2.out[i] = s2;
            m2.E[i] = Ecnt[t];
            m2.cumEH[i + 1] = m2.cumEH[i] + Ecnt[t];
            m2.cumE[i + 1] = m2.cumE[i] + Ecnt[t];
            m2.srcRows[i] = Nsrc2[i];
            m2.dstRows[i] = NS;
            m2.foff[i] = fo;
            m2.tmap[i] = t;
            fo += Nsrc2[i];
        }
        for (int i = 0; i < 4; i++)
            launch_sgemm(srcX2[i], W2s + (size_t)t2[i] * HC * HC, nullptr,
                         feat + (size_t)m2.foff[i] * HC, Nsrc2[i], HC, HC, 0);
    }

    init_bias_kernel<<<4096, 256>>>(s2, b2, make_int4(0, 1, 2, 4), NS * HC);

    build_vd_all<<<dim3((HC * 1 + 127) / 128, 4), 128>>>(W2d, a2d, Vall, HC, 1, 256, m2);
    als_feat_all<<<dim3((NW * 1 + 7) / 8, 4), 256>>>(feat, a2s, als, m2);
    gemv_ald_all<<<dim3((NS + 7) / 8, 4), 256>>>(Vall, ald, m2);

    fill_md_kernel<<<2048, 256>>>(m, den, 6 * AS);
    {
        int tot = m2.cumEH[4];
        edge_pass1_all<<<(tot + 255) / 256, 256>>>(als, ald, ebuf, m, m2);
        edge_pass2_all<<<(tot + 255) / 256, 256>>>(ebuf, m, exbuf, den, m2);
        int totw = m2.cumE[4];
        edge_scatter_all<<<(totw * 32 + 255) / 256, 256>>>(exbuf, den, feat, m2);
    }

    // ---- final LN (no relu) -> output s2 ----
    relu_ln_kernel<<<NS, HC>>>(s2, out_s2, 0);

    // ---- projection head ----
    if (out_size >= NS * (HC + PROJ_H)) {
        launch_sgemm(out_s2, Wp1, bp1, ptmp, NS, PROJ_H, HC, 1);
        launch_sgemm(ptmp, Wp2, bp2, out_prj, NS, PROJ_H, PROJ_H, 0);
    }
}

// round 3
// speedup vs baseline: 1.5876x; 1.1542x over previous
#include <cuda_runtime.h>
#include <cstdint>
#include <math.h>

// ---------------------------------------------------------------------------
// Problem constants
// ---------------------------------------------------------------------------
#define NS 10000
#define NW 30000
#define ND 200
#define DIN 768
#define HC 256
#define PROJ_H 128
#define AS (NW * 4)          // attention-value stride per slot
#define VSZ (DIN * 4)        // V vector stride per slot
#define FEAT_FLOATS (70200 * 256)
#define EH_MAX 2600000

// ---------------------------------------------------------------------------
// Scratch (device globals; no allocation allowed)
// ---------------------------------------------------------------------------
__device__ float g_h_sent[NS * DIN];
__device__ float g_h_word[NW * DIN];
__device__ float g_h_doc [ND * DIN];
__device__ float g_feat  [FEAT_FLOATS];
__device__ float g_V     [6 * VSZ];
__device__ float g_als   [6 * AS];
__device__ float g_ald   [6 * AS];
__device__ float g_m     [6 * AS];
__device__ float g_den   [6 * AS];
__device__ float g_e     [EH_MAX];
__device__ float g_ex    [EH_MAX];
__device__ float g_s1    [NS * HC];
__device__ float g_w1    [NW * HC];
__device__ float g_d1    [ND * HC];
__device__ float g_s2    [NS * HC];
__device__ float g_ptmp  [NS * PROJ_H];

// ---------------------------------------------------------------------------
// metadata struct (passed by value)
// ---------------------------------------------------------------------------
struct ConvMeta {
    const int*   ei[6];      // stacked [2,E] edge arrays
    const float* dstX[6];    // dst-side node features (for ald gemv)
    const float* fptr[6];    // per-slot transformed feature base
    float*       out[6];     // scatter accumulators
    int fstride[6];
    int E[6];
    int cumEH[7];
    int cumE[7];
    int srcRows[6];
    int dstRows[6];
    int tmap[6];             // slot -> weight/type index
    int nt, H, C, K;
};

struct B4 { const float* p[4]; };

// ---------------------------------------------------------------------------
// Double-buffered SGEMM: C[M,N] = act(A[M,K] @ B[K,N] + bias)
// 128x128 tile, BK=16, 256 threads, 8x8/thread, float4, 2-stage smem pipeline
// Requires: K % 16 == 0, N % 128 == 0
// ---------------------------------------------------------------------------
#define GM 128
#define GN 128
#define GK 16

__global__ __launch_bounds__(256, 2)
void sgemm_db(const float* __restrict__ A, const float* __restrict__ B,
              const float* __restrict__ bias, float* __restrict__ C,
              int M, int N, int K, int relu)
{
    __shared__ float As[2][GK][GM];
    __shared__ float Bs[2][GK][GN];
    int tid = threadIdx.x;
    int row0 = blockIdx.y * GM;
    int col0 = blockIdx.x * GN;
    int tx = tid & 15, ty = tid >> 4;
    float acc[8][8] = {};

    const float* Aptr = A + (size_t)row0 * K;
    const float* Bptr = B + col0;

    int a_r[2], a_c[2], b_k[2], b_n[2];
#pragma unroll
    for (int i = 0; i < 2; i++) {
        int idx = tid + i * 256;
        a_r[i] = idx >> 2;
        a_c[i] = (idx & 3) * 4;
        b_k[i] = idx >> 5;
        b_n[i] = (idx & 31) * 4;
    }

    float4 pa[2], pb[2];
#pragma unroll
    for (int i = 0; i < 2; i++) {
        pa[i] = make_float4(0.f, 0.f, 0.f, 0.f);
        if (row0 + a_r[i] < M) pa[i] = *(const float4*)(Aptr + (size_t)a_r[i] * K + a_c[i]);
        pb[i] = *(const float4*)(Bptr + (size_t)b_k[i] * N + b_n[i]);
    }
#pragma unroll
    for (int i = 0; i < 2; i++) {
        As[0][a_c[i] + 0][a_r[i]] = pa[i].x;
        As[0][a_c[i] + 1][a_r[i]] = pa[i].y;
        As[0][a_c[i] + 2][a_r[i]] = pa[i].z;
        As[0][a_c[i] + 3][a_r[i]] = pa[i].w;
        *(float4*)&Bs[0][b_k[i]][b_n[i]] = pb[i];
    }
    __syncthreads();

    int cur = 0;
    for (int k0 = GK; k0 < K; k0 += GK) {
#pragma unroll
        for (int i = 0; i < 2; i++) {
            pa[i] = make_float4(0.f, 0.f, 0.f, 0.f);
            if (row0 + a_r[i] < M) pa[i] = *(const float4*)(Aptr + (size_t)a_r[i] * K + k0 + a_c[i]);
            pb[i] = *(const float4*)(Bptr + (size_t)(k0 + b_k[i]) * N + b_n[i]);
        }
#pragma unroll
        for (int kk = 0; kk < GK; kk++) {
            float a[8], b[8];
            *(float4*)&a[0] = *(const float4*)&As[cur][kk][ty * 8];
            *(float4*)&a[4] = *(const float4*)&As[cur][kk][ty * 8 + 4];
            *(float4*)&b[0] = *(const float4*)&Bs[cur][kk][tx * 8];
            *(float4*)&b[4] = *(const float4*)&Bs[cur][kk][tx * 8 + 4];
#pragma unroll
            for (int i = 0; i < 8; i++)
#pragma unroll
                for (int j = 0; j < 8; j++)
                    acc[i][j] += a[i] * b[j];
        }
        int nxt = cur ^ 1;
#pragma unroll
        for (int i = 0; i < 2; i++) {
            As[nxt][a_c[i] + 0][a_r[i]] = pa[i].x;
            As[nxt][a_c[i] + 1][a_r[i]] = pa[i].y;
            As[nxt][a_c[i] + 2][a_r[i]] = pa[i].z;
            As[nxt][a_c[i] + 3][a_r[i]] = pa[i].w;
            *(float4*)&Bs[nxt][b_k[i]][b_n[i]] = pb[i];
        }
        __syncthreads();
        cur = nxt;
    }
#pragma unroll
    for (int kk = 0; kk < GK; kk++) {
        float a[8], b[8];
        *(float4*)&a[0] = *(const float4*)&As[cur][kk][ty * 8];
        *(float4*)&a[4] = *(const float4*)&As[cur][kk][ty * 8 + 4];
        *(float4*)&b[0] = *(const float4*)&Bs[cur][kk][tx * 8];
        *(float4*)&b[4] = *(const float4*)&Bs[cur][kk][tx * 8 + 4];
#pragma unroll
        for (int i = 0; i < 8; i++)
#pragma unroll
            for (int j = 0; j < 8; j++)
                acc[i][j] += a[i] * b[j];
    }

    float bv[8];
#pragma unroll
    for (int j = 0; j < 8; j++) bv[j] = bias ? bias[col0 + tx * 8 + j] : 0.f;
#pragma unroll
    for (int i = 0; i < 8; i++) {
        int m = row0 + ty * 8 + i;
        if (m >= M) continue;
        float* crow = C + (size_t)m * N + col0 + tx * 8;
        float vv[8];
#pragma unroll
        for (int j = 0; j < 8; j++) {
            float v = acc[i][j] + bv[j];
            if (relu) v = fmaxf(v, 0.f);
            vv[j] = v;
        }
        *(float4*)(crow + 0) = make_float4(vv[0], vv[1], vv[2], vv[3]);
        *(float4*)(crow + 4) = make_float4(vv[4], vv[5], vv[6], vv[7]);
    }
}

// ---------------------------------------------------------------------------
// Multi-B SGEMM: nb independent B matrices of shape [K,256], concatenated along
// N into C[M, nb*256]. grid.x = nb*2. No bias / no relu (feat transforms).
// ---------------------------------------------------------------------------
__global__ __launch_bounds__(256, 2)
void sgemm_db4(const float* __restrict__ A, B4 bsel, float* __restrict__ C,
               int M, int K, int nb)
{
    __shared__ float As[2][GK][GM];
    __shared__ float Bs[2][GK][GN];
    int tid = threadIdx.x;
    int row0 = blockIdx.y * GM;
    int col0 = blockIdx.x * GN;
    int NC = nb * 256;
    const float* B = bsel.p[col0 >> 8] + (col0 & 255);
    int tx = tid & 15, ty = tid >> 4;
    float acc[8][8] = {};

    const float* Aptr = A + (size_t)row0 * K;

    int a_r[2], a_c[2], b_k[2], b_n[2];
#pragma unroll
    for (int i = 0; i < 2; i++) {
        int idx = tid + i * 256;
        a_r[i] = idx >> 2;
        a_c[i] = (idx & 3) * 4;
        b_k[i] = idx >> 5;
        b_n[i] = (idx & 31) * 4;
    }

    float4 pa[2], pb[2];
#pragma unroll
    for (int i = 0; i < 2; i++) {
        pa[i] = make_float4(0.f, 0.f, 0.f, 0.f);
        if (row0 + a_r[i] < M) pa[i] = *(const float4*)(Aptr + (size_t)a_r[i] * K + a_c[i]);
        pb[i] = *(const float4*)(B + (size_t)b_k[i] * 256 + b_n[i]);
    }
#pragma unroll
    for (int i = 0; i < 2; i++) {
        As[0][a_c[i] + 0][a_r[i]] = pa[i].x;
        As[0][a_c[i] + 1][a_r[i]] = pa[i].y;
        As[0][a_c[i] + 2][a_r[i]] = pa[i].z;
        As[0][a_c[i] + 3][a_r[i]] = pa[i].w;
        *(float4*)&Bs[0][b_k[i]][b_n[i]] = pb[i];
    }
    __syncthreads();

    int cur = 0;
    for (int k0 = GK; k0 < K; k0 += GK) {
#pragma unroll
        for (int i = 0; i < 2; i++) {
            pa[i] = make_float4(0.f, 0.f, 0.f, 0.f);
            if (row0 + a_r[i] < M) pa[i] = *(const float4*)(Aptr + (size_t)a_r[i] * K + k0 + a_c[i]);
            pb[i] = *(const float4*)(B + (size_t)(k0 + b_k[i]) * 256 + b_n[i]);
        }
#pragma unroll
        for (int kk = 0; kk < GK; kk++) {
            float a[8], b[8];
            *(float4*)&a[0] = *(const float4*)&As[cur][kk][ty * 8];
            *(float4*)&a[4] = *(const float4*)&As[cur][kk][ty * 8 + 4];
            *(float4*)&b[0] = *(const float4*)&Bs[cur][kk][tx * 8];
            *(float4*)&b[4] = *(const float4*)&Bs[cur][kk][tx * 8 + 4];
#pragma unroll
            for (int i = 0; i < 8; i++)
#pragma unroll
                for (int j = 0; j < 8; j++)
                    acc[i][j] += a[i] * b[j];
        }
        int nxt = cur ^ 1;
#pragma unroll
        for (int i = 0; i < 2; i++) {
            As[nxt][a_c[i] + 0][a_r[i]] = pa[i].x;
            As[nxt][a_c[i] + 1][a_r[i]] = pa[i].y;
            As[nxt][a_c[i] + 2][a_r[i]] = pa[i].z;
            As[nxt][a_c[i] + 3][a_r[i]] = pa[i].w;
            *(float4*)&Bs[nxt][b_k[i]][b_n[i]] = pb[i];
        }
        __syncthreads();
        cur = nxt;
    }
#pragma unroll
    for (int kk = 0; kk < GK; kk++) {
        float a[8], b[8];
        *(float4*)&a[0] = *(const float4*)&As[cur][kk][ty * 8];
        *(float4*)&a[4] = *(const float4*)&As[cur][kk][ty * 8 + 4];
        *(float4*)&b[0] = *(const float4*)&Bs[cur][kk][tx * 8];
        *(float4*)&b[4] = *(const float4*)&Bs[cur][kk][tx * 8 + 4];
#pragma unroll
        for (int i = 0; i < 8; i++)
#pragma unroll
            for (int j = 0; j < 8; j++)
                acc[i][j] += a[i] * b[j];
    }

#pragma unroll
    for (int i = 0; i < 8; i++) {
        int m = row0 + ty * 8 + i;
        if (m >= M) continue;
        float* crow = C + (size_t)m * NC + col0 + tx * 8;
        *(float4*)(crow + 0) = make_float4(acc[i][0], acc[i][1], acc[i][2], acc[i][3]);
        *(float4*)(crow + 4) = make_float4(acc[i][4], acc[i][5], acc[i][6], acc[i][7]);
    }
}

// ---------------------------------------------------------------------------
// build dst-side attention vectors V[slot][k][h] = sum_c Wd[t,k,h*C+c]*ad[t,h,c]
// ---------------------------------------------------------------------------
__global__ void build_vd_all(const float* __restrict__ Wd, const float* __restrict__ ad,
                             float* __restrict__ Vall, int K, int H, int C, ConvMeta md)
{
    int slot = blockIdx.y;
    int typ = md.tmap[slot];
    int idx = blockIdx.x * blockDim.x + threadIdx.x;
    if (idx >= K * H) return;
    int k = idx / H, h = idx - (idx / H) * H;
    const float* w = Wd + (size_t)typ * K * HC + (size_t)k * HC + h * C;
    const float* av = ad + typ * HC + h * C;
    float s = 0.f;
    for (int c = 0; c < C; c++) s += w[c] * av[c];
    Vall[slot * VSZ + k * H + h] = s;
}

// ---------------------------------------------------------------------------
// als[slot][row][h] = sum_c feat[row, h*C+c] * a_s[t, h*C+c]  (warp per (row,h))
// ---------------------------------------------------------------------------
__global__ void als_feat_all(const float* __restrict__ a_s,
                             float* __restrict__ als_all, ConvMeta md)
{
    int slot = blockIdx.y;
    int id = (blockIdx.x * blockDim.x + threadIdx.x) >> 5;
    int lane = threadIdx.x & 31;
    int H = md.H, C = md.C;
    int rows = md.srcRows[slot];
    if (id >= rows * H) return;
    int row = id / H, h = id - (id / H) * H;
    const float* f = md.fptr[slot] + (size_t)row * md.fstride[slot] + h * C;
    const float* a = a_s + md.tmap[slot] * HC + h * C;
    float s = 0.f;
    for (int c = lane; c < C; c += 32) s += f[c] * a[c];
#pragma unroll
    for (int o = 16; o > 0; o >>= 1) s += __shfl_xor_sync(0xffffffffu, s, o);
    if (lane == 0) als_all[slot * AS + row * H + h] = s;
}

// ---------------------------------------------------------------------------
// ald[slot][row][h] = X[row] . V[slot][:,h]     (warp per row, H<=4)
// ---------------------------------------------------------------------------
__global__ void gemv_ald_all(const float* __restrict__ Vall, float* __restrict__ ald_all,
                             ConvMeta md)
{
    int slot = blockIdx.y;
    int warp = (blockIdx.x * blockDim.x + threadIdx.x) >> 5;
    int lane = threadIdx.x & 31;
    int rows = md.dstRows[slot];
    if (warp >= rows) return;
    int K = md.K, H = md.H;
    const float* x = md.dstX[slot] + (size_t)warp * K;
    const float* V = Vall + slot * VSZ;
    float s0 = 0.f, s1 = 0.f, s2 = 0.f, s3 = 0.f;
    for (int k = lane; k < K; k += 32) {
        float xv = x[k];
        const float* v = V + k * H;
        s0 += xv * v[0];
        if (H > 1) { s1 += xv * v[1]; s2 += xv * v[2]; s3 += xv * v[3]; }
    }
#pragma unroll
    for (int o = 16; o > 0; o >>= 1) {
        s0 += __shfl_xor_sync(0xffffffffu, s0, o);
        s1 += __shfl_xor_sync(0xffffffffu, s1, o);
        s2 += __shfl_xor_sync(0xffffffffu, s2, o);
        s3 += __shfl_xor_sync(0xffffffffu, s3, o);
    }
    if (lane == 0) {
        float* o = ald_all + slot * AS + warp * H;
        o[0] = s0;
        if (H > 1) { o[1] = s1; o[2] = s2; o[3] = s3; }
    }
}

// ---------------------------------------------------------------------------
// misc
// ---------------------------------------------------------------------------
__global__ void fill_md_kernel(float* __restrict__ m, float* __restrict__ den, int n)
{
    int i = blockIdx.x * blockDim.x + threadIdx.x;
    for (; i < n; i += gridDim.x * blockDim.x) { m[i] = -INFINITY; den[i] = 0.f; }
}

__global__ void init_bias_kernel(float* __restrict__ out, const float* __restrict__ b,
                                 int4 ts, int total)
{
    int i = blockIdx.x * blockDim.x + threadIdx.x;
    for (; i < total; i += gridDim.x * blockDim.x) {
        int c = i & (HC - 1);
        float v = b[ts.x * HC + c];
        if (ts.y >= 0) v += b[ts.y * HC + c];
        if (ts.z >= 0) v += b[ts.z * HC + c];
        if (ts.w >= 0) v += b[ts.w * HC + c];
        out[i] = v;
    }
}

__device__ __forceinline__ void atomicMaxFloat(float* addr, float val)
{
    if (val >= 0.f) atomicMax((int*)addr, __float_as_int(val));
    else            atomicMin((unsigned int*)addr, __float_as_uint(val));
}

// ---------------------------------------------------------------------------
// edge pipeline (batched over all slots)
// ---------------------------------------------------------------------------
__global__ void edge_pass1_all(const float* __restrict__ als_all, const float* __restrict__ ald_all,
                               float* __restrict__ ebuf, float* __restrict__ m_all, ConvMeta md)
{
    int idx = blockIdx.x * blockDim.x + threadIdx.x;
    if (idx >= md.cumEH[md.nt]) return;
    int slot = 0;
    while (idx >= md.cumEH[slot + 1]) slot++;
    int local = idx - md.cumEH[slot];
    int H = md.H;
    int e, h;
    if (H == 4) { e = local >> 2; h = local & 3; } else { e = local; h = 0; }
    const int* ei = md.ei[slot];
    int s = ei[e], d = ei[md.E[slot] + e];
    float v = als_all[slot * AS + s * H + h] + ald_all[slot * AS + d * H + h];
    v = (v > 0.f) ? v : 0.2f * v;
    ebuf[idx] = v;
    atomicMaxFloat(&m_all[slot * AS + d * H + h], v);
}

__global__ void edge_pass2_all(const float* __restrict__ ebuf, const float* __restrict__ m_all,
                               float* __restrict__ exbuf, float* __restrict__ den_all, ConvMeta md)
{
    int idx = blockIdx.x * blockDim.x + threadIdx.x;
    if (idx >= md.cumEH[md.nt]) return;
    int slot = 0;
    while (idx >= md.cumEH[slot + 1]) slot++;
    int local = idx - md.cumEH[slot];
    int H = md.H;
    int e, h;
    if (H == 4) { e = local >> 2; h = local & 3; } else { e = local; h = 0; }
    const int* ei = md.ei[slot];
    int d = ei[md.E[slot] + e];
    float ex = __expf(ebuf[idx] - m_all[slot * AS + d * H + h]);
    exbuf[idx] = ex;
    atomicAdd(&den_all[slot * AS + d * H + h], ex);
}

__global__ void edge_scatter_all(const float* __restrict__ exbuf, const float* __restrict__ den_all,
                                 ConvMeta md)
{
    int wf = (blockIdx.x * blockDim.x + threadIdx.x) >> 5;
    if (wf >= md.cumE[md.nt]) return;
    int lane = threadIdx.x & 31;
    int slot = 0;
    while (wf >= md.cumE[slot + 1]) slot++;
    int e = wf - md.cumE[slot];
    int H = md.H;
    const int* ei = md.ei[slot];
    int s = ei[e], d = ei[md.E[slot] + e];
    const float4* fs = (const float4*)(md.fptr[slot] + (size_t)s * md.fstride[slot]);
    float* od = md.out[slot] + (size_t)d * HC;
    int ebase = md.cumEH[slot] + e * H;
    const float* dslot = den_all + slot * AS + d * H;
#pragma unroll
    for (int j = 0; j < 2; j++) {
        int i4 = lane + j * 32;
        int base = i4 * 4;
        int h = (H == 4) ? (base >> 6) : 0;
        float alpha = exbuf[ebase + h] / (dslot[h] + 1e-16f);
        float4 v = fs[i4];
        atomicAdd(&od[base + 0], v.x * alpha);
        atomicAdd(&od[base + 1], v.y * alpha);
        atomicAdd(&od[base + 2], v.z * alpha);
        atomicAdd(&od[base + 3], v.w * alpha);
    }
}

// ---------------------------------------------------------------------------
// (optional relu) + LayerNorm over last dim D=256, one 256-thread block per row
// ---------------------------------------------------------------------------
__global__ void relu_ln_kernel(const float* __restrict__ in, float* __restrict__ out, int pre_relu)
{
    int n = blockIdx.x;
    int t = threadIdx.x;
    int lane = t & 31, w = t >> 5;
    float v = in[(size_t)n * HC + t];
    if (pre_relu) v = fmaxf(v, 0.f);
    __shared__ float ws[8];
    float s = v;
#pragma unroll
    for (int o = 16; o > 0; o >>= 1) s += __shfl_xor_sync(0xffffffffu, s, o);
    if (lane == 0) ws[w] = s;
    __syncthreads();
    float mu = 0.f;
#pragma unroll
    for (int i = 0; i < 8; i++) mu += ws[i];
    mu *= (1.f / HC);
    __syncthreads();
    float dv = v - mu;
    s = dv * dv;
#pragma unroll
    for (int o = 16; o > 0; o >>= 1) s += __shfl_xor_sync(0xffffffffu, s, o);
    if (lane == 0) ws[w] = s;
    __syncthreads();
    float var = 0.f;
#pragma unroll
    for (int i = 0; i < 8; i++) var += ws[i];
    var *= (1.f / HC);
    out[(size_t)n * HC + t] = dv * rsqrtf(var + 1e-5f);
}

// ---------------------------------------------------------------------------
// host orchestration
// ---------------------------------------------------------------------------
static inline void launch_sgemm(const float* A, const float* B, const float* bias, float* C,
                                int M, int N, int K, int relu)
{
    dim3 grid(N / GN, (M + GM - 1) / GM);
    sgemm_db<<<grid, 256>>>(A, B, bias, C, M, N, K, relu);
}

extern "C" void kernel_launch(void* const* d_in, const int* in_sizes, int n_in,
                              void* d_out, int out_size)
{
    const float* x_sent = (const float*)d_in[0];
    const float* x_word = (const float*)d_in[1];
    const float* x_doc  = (const float*)d_in[2];
    const int*   ei[6]  = { (const int*)d_in[3], (const int*)d_in[4], (const int*)d_in[5],
                            (const int*)d_in[6], (const int*)d_in[7], (const int*)d_in[8] };
    int Ecnt[6];
    for (int t = 0; t < 6; t++) Ecnt[t] = in_sizes[3 + t] / 2;
    const float* Wls = (const float*)d_in[9];
    const float* bls = (const float*)d_in[10];
    const float* Wlw = (const float*)d_in[11];
    const float* blw = (const float*)d_in[12];
    const float* Wld = (const float*)d_in[13];
    const float* bld = (const float*)d_in[14];
    const float* W1s = (const float*)d_in[15];
    const float* W1d = (const float*)d_in[16];
    const float* a1s = (const float*)d_in[17];
    const float* a1d = (const float*)d_in[18];
    const float* b1  = (const float*)d_in[19];
    const float* W2s = (const float*)d_in[20];
    const float* W2d = (const float*)d_in[21];
    const float* a2s = (const float*)d_in[22];
    const float* a2d = (const float*)d_in[23];
    const float* b2  = (const float*)d_in[24];
    const float* Wp1 = (const float*)d_in[25];
    const float* bp1 = (const float*)d_in[26];
    const float* Wp2 = (const float*)d_in[27];
    const float* bp2 = (const float*)d_in[28];

    float *h_sent, *h_word, *h_doc, *feat, *Vall, *als, *ald, *m, *den, *ebuf, *exbuf;
    float *s1, *w1, *d1, *s2, *ptmp;
    cudaGetSymbolAddress((void**)&h_sent, g_h_sent);
    cudaGetSymbolAddress((void**)&h_word, g_h_word);
    cudaGetSymbolAddress((void**)&h_doc,  g_h_doc);
    cudaGetSymbolAddress((void**)&feat,   g_feat);
    cudaGetSymbolAddress((void**)&Vall,   g_V);
    cudaGetSymbolAddress((void**)&als,    g_als);
    cudaGetSymbolAddress((void**)&ald,    g_ald);
    cudaGetSymbolAddress((void**)&m,      g_m);
    cudaGetSymbolAddress((void**)&den,    g_den);
    cudaGetSymbolAddress((void**)&ebuf,   g_e);
    cudaGetSymbolAddress((void**)&exbuf,  g_ex);
    cudaGetSymbolAddress((void**)&s1,     g_s1);
    cudaGetSymbolAddress((void**)&w1,     g_w1);
    cudaGetSymbolAddress((void**)&d1,     g_d1);
    cudaGetSymbolAddress((void**)&s2,     g_s2);
    cudaGetSymbolAddress((void**)&ptmp,   g_ptmp);

    float* out_s2  = (float*)d_out;
    float* out_prj = out_s2 + (size_t)NS * HC;

    // feat sub-buffers (conv1): sent-batched [NS,1024], word [NW,256], doc [ND,256]
    float* featS = feat;
    float* featW = feat + (size_t)NS * 1024;
    float* featD = featW + (size_t)NW * 256;
    // feat sub-buffers (conv2): s1-batched [NS,512], w1 [NW,256], d1 [ND,256]
    float* featS2 = feat;
    float* featW2 = feat + (size_t)NS * 512;
    float* featD2 = featW2 + (size_t)NW * 256;

    // ---- stage A: input linears + relu ----
    launch_sgemm(x_sent, Wls, bls, h_sent, NS, DIN, DIN, 1);
    launch_sgemm(x_word, Wlw, blw, h_word, NW, DIN, DIN, 1);
    launch_sgemm(x_doc,  Wld, bld, h_doc,  ND, DIN, DIN, 1);

    // ---- conv1 feat GEMMs ----
    {
        B4 b4 = { { W1s + 0 * (size_t)DIN * HC, W1s + 1 * (size_t)DIN * HC,
                    W1s + 3 * (size_t)DIN * HC, W1s + 5 * (size_t)DIN * HC } };
        sgemm_db4<<<dim3(8, (NS + GM - 1) / GM), 256>>>(h_sent, b4, featS, NS, DIN, 4);
        launch_sgemm(h_word, W1s + 2 * (size_t)DIN * HC, nullptr, featW, NW, HC, DIN, 0);
        launch_sgemm(h_doc,  W1s + 4 * (size_t)DIN * HC, nullptr, featD, ND, HC, DIN, 0);
    }

    // ---- conv1 metadata ----
    ConvMeta m1 = {};
    {
        const float* dstX1[6] = { h_sent, h_sent, h_sent, h_word, h_sent, h_doc };
        int          Ndst1[6] = { NS, NS, NS, NW, NS, ND };
        int          Nsrc1[6] = { NS, NS, NW, NS, ND, NS };
        float*       acc1[6]  = { s1, s1, s1, w1, s1, d1 };
        const float* fp1[6]   = { featS + 0, featS + 256, featW, featS + 512, featD, featS + 768 };
        int          fs1[6]   = { 1024, 1024, 256, 1024, 256, 1024 };
        m1.nt = 6; m1.H = 4; m1.C = 64; m1.K = DIN;
        m1.cumEH[0] = 0; m1.cumE[0] = 0;
        for (int t = 0; t < 6; t++) {
            m1.ei[t] = ei[t];
            m1.dstX[t] = dstX1[t];
            m1.fptr[t] = fp1[t];
            m1.fstride[t] = fs1[t];
            m1.out[t] = acc1[t];
            m1.E[t] = Ecnt[t];
            m1.cumEH[t + 1] = m1.cumEH[t] + Ecnt[t] * 4;
            m1.cumE[t + 1] = m1.cumE[t] + Ecnt[t];
            m1.srcRows[t] = Nsrc1[t];
            m1.dstRows[t] = Ndst1[t];
            m1.tmap[t] = t;
        }
    }

    // bias-preloaded accumulators
    init_bias_kernel<<<4096, 256>>>(s1, b1, make_int4(0, 1, 2, 4), NS * HC);
    init_bias_kernel<<<4096, 256>>>(w1, b1, make_int4(3, -1, -1, -1), NW * HC);
    init_bias_kernel<<<256,  256>>>(d1, b1, make_int4(5, -1, -1, -1), ND * HC);

    // attention values
    build_vd_all<<<dim3((DIN * 4 + 127) / 128, 6), 128>>>(W1d, a1d, Vall, DIN, 4, 64, m1);
    als_feat_all<<<dim3((NW * 4 + 7) / 8, 6), 256>>>(a1s, als, m1);
    gemv_ald_all<<<dim3((NW + 7) / 8, 6), 256>>>(Vall, ald, m1);

    // edge softmax + scatter
    fill_md_kernel<<<2048, 256>>>(m, den, 6 * AS);
    {
        int tot = m1.cumEH[6];
        edge_pass1_all<<<(tot + 255) / 256, 256>>>(als, ald, ebuf, m, m1);
        edge_pass2_all<<<(tot + 255) / 256, 256>>>(ebuf, m, exbuf, den, m1);
        int totw = m1.cumE[6];
        edge_scatter_all<<<(totw * 32 + 255) / 256, 256>>>(exbuf, den, m1);
    }

    // ---- relu + LN ----
    relu_ln_kernel<<<NS, HC>>>(s1, s1, 1);
    relu_ln_kernel<<<NW, HC>>>(w1, w1, 1);
    relu_ln_kernel<<<ND, HC>>>(d1, d1, 1);

    // ---- conv2 feat GEMMs ----
    {
        B4 b4 = { { W2s + 0 * (size_t)HC * HC, W2s + 1 * (size_t)HC * HC, nullptr, nullptr } };
        sgemm_db4<<<dim3(4, (NS + GM - 1) / GM), 256>>>(s1, b4, featS2, NS, HC, 2);
        launch_sgemm(w1, W2s + 2 * (size_t)HC * HC, nullptr, featW2, NW, HC, HC, 0);
        launch_sgemm(d1, W2s + 4 * (size_t)HC * HC, nullptr, featD2, ND, HC, HC, 0);
    }

    // ---- conv2 metadata (types {0,1,2,4} -> sentences) ----
    ConvMeta m2 = {};
    {
        const int    t2[4]    = { 0, 1, 2, 4 };
        int          Nsrc2[4] = { NS, NS, NW, ND };
        const float* fp2[4]   = { featS2 + 0, featS2 + 256, featW2, featD2 };
        int          fs2[4]   = { 512, 512, 256, 256 };
        m2.nt = 4; m2.H = 1; m2.C = 256; m2.K = HC;
        m2.cumEH[0] = 0; m2.cumE[0] = 0;
        for (int i = 0; i < 4; i++) {
            int t = t2[i];
            m2.ei[i] = ei[t];
            m2.dstX[i] = s1;
            m2.fptr[i] = fp2[i];
            m2.fstride[i] = fs2[i];
            m2.out[i] = s2;
            m2.E[i] = Ecnt[t];
            m2.cumEH[i + 1] = m2.cumEH[i] + Ecnt[t];
            m2.cumE[i + 1] = m2.cumE[i] + Ecnt[t];
            m2.srcRows[i] = Nsrc2[i];
            m2.dstRows[i] = NS;
            m2.tmap[i] = t;
        }
    }

    init_bias_kernel<<<4096, 256>>>(s2, b2, make_int4(0, 1, 2, 4), NS * HC);

    build_vd_all<<<dim3((HC * 1 + 127) / 128, 4), 128>>>(W2d, a2d, Vall, HC, 1, 256, m2);
    als_feat_all<<<dim3((NW * 1 + 7) / 8, 4), 256>>>(a2s, als, m2);
    gemv_ald_all<<<dim3((NS + 7) / 8, 4), 256>>>(Vall, ald, m2);

    fill_md_kernel<<<2048, 256>>>(m, den, 6 * AS);
    {
        int tot = m2.cumEH[4];
        edge_pass1_all<<<(tot + 255) / 256, 256>>>(als, ald, ebuf, m, m2);
        edge_pass2_all<<<(tot + 255) / 256, 256>>>(ebuf, m, exbuf, den, m2);
        int totw = m2.cumE[4];
        edge_scatter_all<<<(totw * 32 + 255) / 256, 256>>>(exbuf, den, m2);
    }

    // ---- final LN (no relu) -> output s2 ----
    relu_ln_kernel<<<NS, HC>>>(s2, out_s2, 0);

    // ---- projection head ----
    if (out_size >= NS * (HC + PROJ_H)) {
        launch_sgemm(out_s2, Wp1, bp1, ptmp, NS, PROJ_H, HC, 1);
        launch_sgemm(ptmp, Wp2, bp2, out_prj, NS, PROJ_H, PROJ_H, 0);
    }
}

// round 4
// speedup vs baseline: 2.7460x; 1.7297x over previous
#include <cuda_runtime.h>
#include <cstdint>
#include <math.h>

// ---------------------------------------------------------------------------
// Problem constants
// ---------------------------------------------------------------------------
#define NS 10000
#define NW 30000
#define ND 200
#define DIN 768
#define HC 256
#define PROJ_H 128
#define AS (NW * 4)          // attention-value stride per slot
#define VSZ (DIN * 4)        // V vector stride per slot
#define FEAT_FLOATS (70200 * 256)
#define EH_MAX 2600000

// ---------------------------------------------------------------------------
// Scratch (device globals; no allocation allowed)
// ---------------------------------------------------------------------------
__device__ float g_h_sent[NS * DIN];
__device__ float g_h_word[NW * DIN];
__device__ float g_h_doc [ND * DIN];
__device__ float g_feat  [FEAT_FLOATS];
__device__ float g_V     [6 * VSZ];
__device__ float g_als   [6 * AS];
__device__ float g_ald   [6 * AS];
__device__ float g_m     [6 * AS];
__device__ float g_den   [6 * AS];
__device__ float g_e     [EH_MAX];
__device__ float g_ex    [EH_MAX];
__device__ float g_s1    [NS * HC];
__device__ float g_w1    [NW * HC];
__device__ float g_d1    [ND * HC];
__device__ float g_s2    [NS * HC];
__device__ float g_ptmp  [NS * PROJ_H];

// ---------------------------------------------------------------------------
// metadata struct (passed by value)
// ---------------------------------------------------------------------------
struct ConvMeta {
    const int*   ei[6];      // stacked [2,E] edge arrays
    const float* dstX[6];    // dst-side node features (for ald gemv)
    const float* fptr[6];    // per-slot transformed feature base
    float*       out[6];     // scatter accumulators
    int fstride[6];
    int E[6];
    int cumEH[7];
    int cumE[7];
    int srcRows[6];
    int dstRows[6];
    int tmap[6];             // slot -> weight/type index
    int nt, H, C, K;
};

struct B8 { const float* p[8]; };

// ---------------------------------------------------------------------------
// TF32 tensor-core GEMM: C[M, ldc] = act(A[M,K] @ B + bias)
// 128x128 block tile, BK=16, 256 threads (8 warps), warp tile 64x32,
// mma.sync.aligned.m16n8k8.row.col.f32.tf32.tf32.f32.
// Per-column-block B pointer table (bp.p[blockIdx.x]) with row stride bstride.
// Requires K % 16 == 0. M tail handled by guards.
// ---------------------------------------------------------------------------
__device__ __forceinline__ uint32_t f2tf(float x)
{
    uint32_t r;
    asm("cvt.rna.tf32.f32 %0, %1;" : "=r"(r) : "f"(x));
    return r;
}

__device__ __forceinline__ void mma_tf32(float* c, const uint32_t* a, const uint32_t* b)
{
    asm volatile(
        "mma.sync.aligned.m16n8k8.row.col.f32.tf32.tf32.f32 "
        "{%0,%1,%2,%3}, {%4,%5,%6,%7}, {%8,%9}, {%0,%1,%2,%3};"
        : "+f"(c[0]), "+f"(c[1]), "+f"(c[2]), "+f"(c[3])
        : "r"(a[0]), "r"(a[1]), "r"(a[2]), "r"(a[3]), "r"(b[0]), "r"(b[1]));
}

#define TBK 16

__global__ __launch_bounds__(256, 2)
void tgemm(const float* __restrict__ A, B8 bp, const float* __restrict__ bias,
           float* __restrict__ C, int M, int K, int bstride, int ldc, int relu)
{
    __shared__ float As[128][20];    // [m][k], pad to 20 (conflict-free frag loads)
    __shared__ float Bs[TBK][132];   // [k][n], pad to 132

    int tid = threadIdx.x;
    int row0 = blockIdx.y * 128;
    int col0 = blockIdx.x * 128;
    const float* B = bp.p[blockIdx.x];

    int lane = tid & 31, warp = tid >> 5;
    int g = lane >> 2, t = lane & 3;
    int wr = warp & 1, wc = warp >> 1;   // 2 warp-rows x 4 warp-cols

    float acc[4][4][4] = {};             // [mt][nt][4]

    // global->smem load indices (2 float4 per thread each for A and B)
    int a_r[2], a_c[2], b_r[2], b_c[2];
#pragma unroll
    for (int i = 0; i < 2; i++) {
        int idx = tid + i * 256;
        a_r[i] = idx >> 2;          // 0..127
        a_c[i] = (idx & 3) * 4;     // 0,4,8,12
        b_r[i] = idx >> 5;          // 0..15
        b_c[i] = (idx & 31) * 4;    // 0..124
    }

    const float* Aptr = A + (size_t)row0 * K;

    float4 pa[2], pb[2];
#pragma unroll
    for (int i = 0; i < 2; i++) {
        pa[i] = make_float4(0.f, 0.f, 0.f, 0.f);
        if (row0 + a_r[i] < M) pa[i] = *(const float4*)(Aptr + (size_t)a_r[i] * K + a_c[i]);
        pb[i] = *(const float4*)(B + (size_t)b_r[i] * bstride + b_c[i]);
    }
#pragma unroll
    for (int i = 0; i < 2; i++) {
        *(float4*)&As[a_r[i]][a_c[i]] = pa[i];
        *(float4*)&Bs[b_r[i]][b_c[i]] = pb[i];
    }
    __syncthreads();

    for (int k0 = TBK; k0 <= K; k0 += TBK) {
        // prefetch next tile (if any)
        if (k0 < K) {
#pragma unroll
            for (int i = 0; i < 2; i++) {
                pa[i] = make_float4(0.f, 0.f, 0.f, 0.f);
                if (row0 + a_r[i] < M) pa[i] = *(const float4*)(Aptr + (size_t)a_r[i] * K + k0 + a_c[i]);
                pb[i] = *(const float4*)(B + (size_t)(k0 + b_r[i]) * bstride + b_c[i]);
            }
        }
        // compute 2 k8-steps from smem
#pragma unroll
        for (int ks = 0; ks < 2; ks++) {
            int kb = ks * 8;
            uint32_t af[4][4], bf[4][2];
#pragma unroll
            for (int mt = 0; mt < 4; mt++) {
                int r = wr * 64 + mt * 16 + g;
                af[mt][0] = f2tf(As[r][kb + t]);
                af[mt][1] = f2tf(As[r + 8][kb + t]);
                af[mt][2] = f2tf(As[r][kb + t + 4]);
                af[mt][3] = f2tf(As[r + 8][kb + t + 4]);
            }
#pragma unroll
            for (int nt = 0; nt < 4; nt++) {
                int c = wc * 32 + nt * 8 + g;
                bf[nt][0] = f2tf(Bs[kb + t][c]);
                bf[nt][1] = f2tf(Bs[kb + t + 4][c]);
            }
#pragma unroll
            for (int mt = 0; mt < 4; mt++)
#pragma unroll
                for (int nt = 0; nt < 4; nt++)
                    mma_tf32(acc[mt][nt], af[mt], bf[nt]);
        }
        __syncthreads();
        if (k0 < K) {
#pragma unroll
            for (int i = 0; i < 2; i++) {
                *(float4*)&As[a_r[i]][a_c[i]] = pa[i];
                *(float4*)&Bs[b_r[i]][b_c[i]] = pb[i];
            }
            __syncthreads();
        }
    }

    // epilogue: acc[mt][nt] -> C rows (wr*64+mt*16+g, +8), cols (wc*32+nt*8+2t, +1)
#pragma unroll
    for (int mt = 0; mt < 4; mt++) {
        int m0 = row0 + wr * 64 + mt * 16 + g;
#pragma unroll
        for (int nt = 0; nt < 4; nt++) {
            int cg = col0 + wc * 32 + nt * 8 + 2 * t;
            float b0 = bias ? bias[cg] : 0.f;
            float b1 = bias ? bias[cg + 1] : 0.f;
            if (m0 < M) {
                float v0 = acc[mt][nt][0] + b0;
                float v1 = acc[mt][nt][1] + b1;
                if (relu) { v0 = fmaxf(v0, 0.f); v1 = fmaxf(v1, 0.f); }
                float* p = C + (size_t)m0 * ldc + cg;
                p[0] = v0; p[1] = v1;
            }
            if (m0 + 8 < M) {
                float v0 = acc[mt][nt][2] + b0;
                float v1 = acc[mt][nt][3] + b1;
                if (relu) { v0 = fmaxf(v0, 0.f); v1 = fmaxf(v1, 0.f); }
                float* p = C + (size_t)(m0 + 8) * ldc + cg;
                p[0] = v0; p[1] = v1;
            }
        }
    }
}

// ---------------------------------------------------------------------------
// build dst-side attention vectors V[slot][k][h] = sum_c Wd[t,k,h*C+c]*ad[t,h,c]
// ---------------------------------------------------------------------------
__global__ void build_vd_all(const float* __restrict__ Wd, const float* __restrict__ ad,
                             float* __restrict__ Vall, int K, int H, int C, ConvMeta md)
{
    int slot = blockIdx.y;
    int typ = md.tmap[slot];
    int idx = blockIdx.x * blockDim.x + threadIdx.x;
    if (idx >= K * H) return;
    int k = idx / H, h = idx - (idx / H) * H;
    const float* w = Wd + (size_t)typ * K * HC + (size_t)k * HC + h * C;
    const float* av = ad + typ * HC + h * C;
    float s = 0.f;
    for (int c = 0; c < C; c++) s += w[c] * av[c];
    Vall[slot * VSZ + k * H + h] = s;
}

// ---------------------------------------------------------------------------
// als[slot][row][h] = sum_c feat[row, h*C+c] * a_s[t, h*C+c]  (warp per (row,h))
// ---------------------------------------------------------------------------
__global__ void als_feat_all(const float* __restrict__ a_s,
                             float* __restrict__ als_all, ConvMeta md)
{
    int slot = blockIdx.y;
    int id = (blockIdx.x * blockDim.x + threadIdx.x) >> 5;
    int lane = threadIdx.x & 31;
    int H = md.H, C = md.C;
    int rows = md.srcRows[slot];
    if (id >= rows * H) return;
    int row = id / H, h = id - (id / H) * H;
    const float* f = md.fptr[slot] + (size_t)row * md.fstride[slot] + h * C;
    const float* a = a_s + md.tmap[slot] * HC + h * C;
    float s = 0.f;
    for (int c = lane; c < C; c += 32) s += f[c] * a[c];
#pragma unroll
    for (int o = 16; o > 0; o >>= 1) s += __shfl_xor_sync(0xffffffffu, s, o);
    if (lane == 0) als_all[slot * AS + row * H + h] = s;
}

// ---------------------------------------------------------------------------
// ald[slot][row][h] = X[row] . V[slot][:,h]     (warp per row, H<=4)
// ---------------------------------------------------------------------------
__global__ void gemv_ald_all(const float* __restrict__ Vall, float* __restrict__ ald_all,
                             ConvMeta md)
{
    int slot = blockIdx.y;
    int warp = (blockIdx.x * blockDim.x + threadIdx.x) >> 5;
    int lane = threadIdx.x & 31;
    int rows = md.dstRows[slot];
    if (warp >= rows) return;
    int K = md.K, H = md.H;
    const float* x = md.dstX[slot] + (size_t)warp * K;
    const float* V = Vall + slot * VSZ;
    float s0 = 0.f, s1 = 0.f, s2 = 0.f, s3 = 0.f;
    for (int k = lane; k < K; k += 32) {
        float xv = x[k];
        const float* v = V + k * H;
        s0 += xv * v[0];
        if (H > 1) { s1 += xv * v[1]; s2 += xv * v[2]; s3 += xv * v[3]; }
    }
#pragma unroll
    for (int o = 16; o > 0; o >>= 1) {
        s0 += __shfl_xor_sync(0xffffffffu, s0, o);
        s1 += __shfl_xor_sync(0xffffffffu, s1, o);
        s2 += __shfl_xor_sync(0xffffffffu, s2, o);
        s3 += __shfl_xor_sync(0xffffffffu, s3, o);
    }
    if (lane == 0) {
        float* o = ald_all + slot * AS + warp * H;
        o[0] = s0;
        if (H > 1) { o[1] = s1; o[2] = s2; o[3] = s3; }
    }
}

// ---------------------------------------------------------------------------
// misc
// ---------------------------------------------------------------------------
__global__ void fill_md_kernel(float* __restrict__ m, float* __restrict__ den, int n)
{
    int i = blockIdx.x * blockDim.x + threadIdx.x;
    for (; i < n; i += gridDim.x * blockDim.x) { m[i] = -INFINITY; den[i] = 0.f; }
}

__global__ void init_bias_kernel(float* __restrict__ out, const float* __restrict__ b,
                                 int4 ts, int total)
{
    int i = blockIdx.x * blockDim.x + threadIdx.x;
    for (; i < total; i += gridDim.x * blockDim.x) {
        int c = i & (HC - 1);
        float v = b[ts.x * HC + c];
        if (ts.y >= 0) v += b[ts.y * HC + c];
        if (ts.z >= 0) v += b[ts.z * HC + c];
        if (ts.w >= 0) v += b[ts.w * HC + c];
        out[i] = v;
    }
}

__device__ __forceinline__ void atomicMaxFloat(float* addr, float val)
{
    if (val >= 0.f) atomicMax((int*)addr, __float_as_int(val));
    else            atomicMin((unsigned int*)addr, __float_as_uint(val));
}

// ---------------------------------------------------------------------------
// edge pipeline (batched over all slots)
// ---------------------------------------------------------------------------
__global__ void edge_pass1_all(const float* __restrict__ als_all, const float* __restrict__ ald_all,
                               float* __restrict__ ebuf, float* __restrict__ m_all, ConvMeta md)
{
    int idx = blockIdx.x * blockDim.x + threadIdx.x;
    if (idx >= md.cumEH[md.nt]) return;
    int slot = 0;
    while (idx >= md.cumEH[slot + 1]) slot++;
    int local = idx - md.cumEH[slot];
    int H = md.H;
    int e, h;
    if (H == 4) { e = local >> 2; h = local & 3; } else { e = local; h = 0; }
    const int* ei = md.ei[slot];
    int s = ei[e], d = ei[md.E[slot] + e];
    float v = als_all[slot * AS + s * H + h] + ald_all[slot * AS + d * H + h];
    v = (v > 0.f) ? v : 0.2f * v;
    ebuf[idx] = v;
    atomicMaxFloat(&m_all[slot * AS + d * H + h], v);
}

__global__ void edge_pass2_all(const float* __restrict__ ebuf, const float* __restrict__ m_all,
                               float* __restrict__ exbuf, float* __restrict__ den_all, ConvMeta md)
{
    int idx = blockIdx.x * blockDim.x + threadIdx.x;
    if (idx >= md.cumEH[md.nt]) return;
    int slot = 0;
    while (idx >= md.cumEH[slot + 1]) slot++;
    int local = idx - md.cumEH[slot];
    int H = md.H;
    int e, h;
    if (H == 4) { e = local >> 2; h = local & 3; } else { e = local; h = 0; }
    const int* ei = md.ei[slot];
    int d = ei[md.E[slot] + e];
    float ex = __expf(ebuf[idx] - m_all[slot * AS + d * H + h]);
    exbuf[idx] = ex;
    atomicAdd(&den_all[slot * AS + d * H + h], ex);
}

__global__ void edge_scatter_all(const float* __restrict__ exbuf, const float* __restrict__ den_all,
                                 ConvMeta md)
{
    int wf = (blockIdx.x * blockDim.x + threadIdx.x) >> 5;
    if (wf >= md.cumE[md.nt]) return;
    int lane = threadIdx.x & 31;
    int slot = 0;
    while (wf >= md.cumE[slot + 1]) slot++;
    int e = wf - md.cumE[slot];
    int H = md.H;
    const int* ei = md.ei[slot];
    int s = ei[e], d = ei[md.E[slot] + e];
    const float4* fs = (const float4*)(md.fptr[slot] + (size_t)s * md.fstride[slot]);
    float* od = md.out[slot] + (size_t)d * HC;
    int ebase = md.cumEH[slot] + e * H;
    const float* dslot = den_all + slot * AS + d * H;
#pragma unroll
    for (int j = 0; j < 2; j++) {
        int i4 = lane + j * 32;
        int base = i4 * 4;
        int h = (H == 4) ? (base >> 6) : 0;
        float alpha = exbuf[ebase + h] / (dslot[h] + 1e-16f);
        float4 v = fs[i4];
        atomicAdd(&od[base + 0], v.x * alpha);
        atomicAdd(&od[base + 1], v.y * alpha);
        atomicAdd(&od[base + 2], v.z * alpha);
        atomicAdd(&od[base + 3], v.w * alpha);
    }
}

// ---------------------------------------------------------------------------
// (optional relu) + LayerNorm over last dim D=256, one 256-thread block per row
// ---------------------------------------------------------------------------
__global__ void relu_ln_kernel(const float* __restrict__ in, float* __restrict__ out, int pre_relu)
{
    int n = blockIdx.x;
    int t = threadIdx.x;
    int lane = t & 31, w = t >> 5;
    float v = in[(size_t)n * HC + t];
    if (pre_relu) v = fmaxf(v, 0.f);
    __shared__ float ws[8];
    float s = v;
#pragma unroll
    for (int o = 16; o > 0; o >>= 1) s += __shfl_xor_sync(0xffffffffu, s, o);
    if (lane == 0) ws[w] = s;
    __syncthreads();
    float mu = 0.f;
#pragma unroll
    for (int i = 0; i < 8; i++) mu += ws[i];
    mu *= (1.f / HC);
    __syncthreads();
    float dv = v - mu;
    s = dv * dv;
#pragma unroll
    for (int o = 16; o > 0; o >>= 1) s += __shfl_xor_sync(0xffffffffu, s, o);
    if (lane == 0) ws[w] = s;
    __syncthreads();
    float var = 0.f;
#pragma unroll
    for (int i = 0; i < 8; i++) var += ws[i];
    var *= (1.f / HC);
    out[(size_t)n * HC + t] = dv * rsqrtf(var + 1e-5f);
}

// ---------------------------------------------------------------------------
// host orchestration
// ---------------------------------------------------------------------------
// Single-B tgemm launch: N columns of B (row stride = N), bias/relu optional.
static inline void launch_tgemm(const float* A, const float* B, const float* bias, float* C,
                                int M, int N, int K, int relu)
{
    B8 bp = {};
    int gx = N / 128;
    for (int i = 0; i < gx; i++) bp.p[i] = B + i * 128;
    dim3 grid(gx, (M + 127) / 128);
    tgemm<<<grid, 256>>>(A, bp, bias, C, M, K, N, N, relu);
}

extern "C" void kernel_launch(void* const* d_in, const int* in_sizes, int n_in,
                              void* d_out, int out_size)
{
    const float* x_sent = (const float*)d_in[0];
    const float* x_word = (const float*)d_in[1];
    const float* x_doc  = (const float*)d_in[2];
    const int*   ei[6]  = { (const int*)d_in[3], (const int*)d_in[4], (const int*)d_in[5],
                            (const int*)d_in[6], (const int*)d_in[7], (const int*)d_in[8] };
    int Ecnt[6];
    for (int t = 0; t < 6; t++) Ecnt[t] = in_sizes[3 + t] / 2;
    const float* Wls = (const float*)d_in[9];
    const float* bls = (const float*)d_in[10];
    const float* Wlw = (const float*)d_in[11];
    const float* blw = (const float*)d_in[12];
    const float* Wld = (const float*)d_in[13];
    const float* bld = (const float*)d_in[14];
    const float* W1s = (const float*)d_in[15];
    const float* W1d = (const float*)d_in[16];
    const float* a1s = (const float*)d_in[17];
    const float* a1d = (const float*)d_in[18];
    const float* b1  = (const float*)d_in[19];
    const float* W2s = (const float*)d_in[20];
    const float* W2d = (const float*)d_in[21];
    const float* a2s = (const float*)d_in[22];
    const float* a2d = (const float*)d_in[23];
    const float* b2  = (const float*)d_in[24];
    const float* Wp1 = (const float*)d_in[25];
    const float* bp1 = (const float*)d_in[26];
    const float* Wp2 = (const float*)d_in[27];
    const float* bp2 = (const float*)d_in[28];

    float *h_sent, *h_word, *h_doc, *feat, *Vall, *als, *ald, *m, *den, *ebuf, *exbuf;
    float *s1, *w1, *d1, *s2, *ptmp;
    cudaGetSymbolAddress((void**)&h_sent, g_h_sent);
    cudaGetSymbolAddress((void**)&h_word, g_h_word);
    cudaGetSymbolAddress((void**)&h_doc,  g_h_doc);
    cudaGetSymbolAddress((void**)&feat,   g_feat);
    cudaGetSymbolAddress((void**)&Vall,   g_V);
    cudaGetSymbolAddress((void**)&als,    g_als);
    cudaGetSymbolAddress((void**)&ald,    g_ald);
    cudaGetSymbolAddress((void**)&m,      g_m);
    cudaGetSymbolAddress((void**)&den,    g_den);
    cudaGetSymbolAddress((void**)&ebuf,   g_e);
    cudaGetSymbolAddress((void**)&exbuf,  g_ex);
    cudaGetSymbolAddress((void**)&s1,     g_s1);
    cudaGetSymbolAddress((void**)&w1,     g_w1);
    cudaGetSymbolAddress((void**)&d1,     g_d1);
    cudaGetSymbolAddress((void**)&s2,     g_s2);
    cudaGetSymbolAddress((void**)&ptmp,   g_ptmp);

    float* out_s2  = (float*)d_out;
    float* out_prj = out_s2 + (size_t)NS * HC;

    // feat sub-buffers (conv1): sent-batched [NS,1024], word [NW,256], doc [ND,256]
    float* featS = feat;
    float* featW = feat + (size_t)NS * 1024;
    float* featD = featW + (size_t)NW * 256;
    // feat sub-buffers (conv2): s1-batched [NS,512], w1 [NW,256], d1 [ND,256]
    float* featS2 = feat;
    float* featW2 = feat + (size_t)NS * 512;
    float* featD2 = featW2 + (size_t)NW * 256;

    // ---- stage A: input linears + relu (tf32 tensor cores) ----
    launch_tgemm(x_sent, Wls, bls, h_sent, NS, DIN, DIN, 1);
    launch_tgemm(x_word, Wlw, blw, h_word, NW, DIN, DIN, 1);
    launch_tgemm(x_doc,  Wld, bld, h_doc,  ND, DIN, DIN, 1);

    // ---- conv1 feat GEMMs ----
    {
        // sent-sourced types {0,1,3,5} batched along N: C = featS [NS,1024]
        B8 bp = {};
        const int st[4] = { 0, 1, 3, 5 };
        for (int i = 0; i < 8; i++)
            bp.p[i] = W1s + (size_t)st[i >> 1] * DIN * HC + (i & 1) * 128;
        tgemm<<<dim3(8, (NS + 127) / 128), 256>>>(h_sent, bp, nullptr, featS, NS, DIN, HC, 1024, 0);
        launch_tgemm(h_word, W1s + 2 * (size_t)DIN * HC, nullptr, featW, NW, HC, DIN, 0);
        launch_tgemm(h_doc,  W1s + 4 * (size_t)DIN * HC, nullptr, featD, ND, HC, DIN, 0);
    }

    // ---- conv1 metadata ----
    ConvMeta m1 = {};
    {
        const float* dstX1[6] = { h_sent, h_sent, h_sent, h_word, h_sent, h_doc };
        int          Ndst1[6] = { NS, NS, NS, NW, NS, ND };
        int          Nsrc1[6] = { NS, NS, NW, NS, ND, NS };
        float*       acc1[6]  = { s1, s1, s1, w1, s1, d1 };
        const float* fp1[6]   = { featS + 0, featS + 256, featW, featS + 512, featD, featS + 768 };
        int          fs1[6]   = { 1024, 1024, 256, 1024, 256, 1024 };
        m1.nt = 6; m1.H = 4; m1.C = 64; m1.K = DIN;
        m1.cumEH[0] = 0; m1.cumE[0] = 0;
        for (int t = 0; t < 6; t++) {
            m1.ei[t] = ei[t];
            m1.dstX[t] = dstX1[t];
            m1.fptr[t] = fp1[t];
            m1.fstride[t] = fs1[t];
            m1.out[t] = acc1[t];
            m1.E[t] = Ecnt[t];
            m1.cumEH[t + 1] = m1.cumEH[t] + Ecnt[t] * 4;
            m1.cumE[t + 1] = m1.cumE[t] + Ecnt[t];
            m1.srcRows[t] = Nsrc1[t];
            m1.dstRows[t] = Ndst1[t];
            m1.tmap[t] = t;
        }
    }

    // bias-preloaded accumulators
    init_bias_kernel<<<4096, 256>>>(s1, b1, make_int4(0, 1, 2, 4), NS * HC);
    init_bias_kernel<<<4096, 256>>>(w1, b1, make_int4(3, -1, -1, -1), NW * HC);
    init_bias_kernel<<<256,  256>>>(d1, b1, make_int4(5, -1, -1, -1), ND * HC);

    // attention values (fp32 — keep logits full precision)
    build_vd_all<<<dim3((DIN * 4 + 127) / 128, 6), 128>>>(W1d, a1d, Vall, DIN, 4, 64, m1);
    als_feat_all<<<dim3((NW * 4 + 7) / 8, 6), 256>>>(a1s, als, m1);
    gemv_ald_all<<<dim3((NW + 7) / 8, 6), 256>>>(Vall, ald, m1);

    // edge softmax + scatter
    fill_md_kernel<<<2048, 256>>>(m, den, 6 * AS);
    {
        int tot = m1.cumEH[6];
        edge_pass1_all<<<(tot + 255) / 256, 256>>>(als, ald, ebuf, m, m1);
        edge_pass2_all<<<(tot + 255) / 256, 256>>>(ebuf, m, exbuf, den, m1);
        int totw = m1.cumE[6];
        edge_scatter_all<<<(totw * 32 + 255) / 256, 256>>>(exbuf, den, m1);
    }

    // ---- relu + LN ----
    relu_ln_kernel<<<NS, HC>>>(s1, s1, 1);
    relu_ln_kernel<<<NW, HC>>>(w1, w1, 1);
    relu_ln_kernel<<<ND, HC>>>(d1, d1, 1);

    // ---- conv2 feat GEMMs ----
    {
        B8 bp = {};
        const int st[2] = { 0, 1 };
        for (int i = 0; i < 4; i++)
            bp.p[i] = W2s + (size_t)st[i >> 1] * HC * HC + (i & 1) * 128;
        tgemm<<<dim3(4, (NS + 127) / 128), 256>>>(s1, bp, nullptr, featS2, NS, HC, HC, 512, 0);
        launch_tgemm(w1, W2s + 2 * (size_t)HC * HC, nullptr, featW2, NW, HC, HC, 0);
        launch_tgemm(d1, W2s + 4 * (size_t)HC * HC, nullptr, featD2, ND, HC, HC, 0);
    }

    // ---- conv2 metadata (types {0,1,2,4} -> sentences) ----
    ConvMeta m2 = {};
    {
        const int    t2[4]    = { 0, 1, 2, 4 };
        int          Nsrc2[4] = { NS, NS, NW, ND };
        const float* fp2[4]   = { featS2 + 0, featS2 + 256, featW2, featD2 };
        int          fs2[4]   = { 512, 512, 256, 256 };
        m2.nt = 4; m2.H = 1; m2.C = 256; m2.K = HC;
        m2.cumEH[0] = 0; m2.cumE[0] = 0;
        for (int i = 0; i < 4; i++) {
            int t = t2[i];
            m2.ei[i] = ei[t];
            m2.dstX[i] = s1;
            m2.fptr[i] = fp2[i];
            m2.fstride[i] = fs2[i];
            m2.out[i] = s2;
            m2.E[i] = Ecnt[t];
            m2.cumEH[i + 1] = m2.cumEH[i] + Ecnt[t];
            m2.cumE[i + 1] = m2.cumE[i] + Ecnt[t];
            m2.srcRows[i] = Nsrc2[i];
            m2.dstRows[i] = NS;
            m2.tmap[i] = t;
        }
    }

    init_bias_kernel<<<4096, 256>>>(s2, b2, make_int4(0, 1, 2, 4), NS * HC);

    build_vd_all<<<dim3((HC * 1 + 127) / 128, 4), 128>>>(W2d, a2d, Vall, HC, 1, 256, m2);
    als_feat_all<<<dim3((NW * 1 + 7) / 8, 4), 256>>>(a2s, als, m2);
    gemv_ald_all<<<dim3((NS + 7) / 8, 4), 256>>>(Vall, ald, m2);

    fill_md_kernel<<<2048, 256>>>(m, den, 6 * AS);
    {
        int tot = m2.cumEH[4];
        edge_pass1_all<<<(tot + 255) / 256, 256>>>(als, ald, ebuf, m, m2);
        edge_pass2_all<<<(tot + 255) / 256, 256>>>(ebuf, m, exbuf, den, m2);
        int totw = m2.cumE[4];
        edge_scatter_all<<<(totw * 32 + 255) / 256, 256>>>(exbuf, den, m2);
    }

    // ---- final LN (no relu) -> output s2 ----
    relu_ln_kernel<<<NS, HC>>>(s2, out_s2, 0);

    // ---- projection head ----
    if (out_size >= NS * (HC + PROJ_H)) {
        launch_tgemm(out_s2, Wp1, bp1, ptmp, NS, PROJ_H, HC, 1);
        launch_tgemm(ptmp, Wp2, bp2, out_prj, NS, PROJ_H, PROJ_H, 0);
    }
}

// round 5
// speedup vs baseline: 2.9751x; 1.0834x over previous
#include <cuda_runtime.h>
#include <cstdint>
#include <math.h>

// ---------------------------------------------------------------------------
// Problem constants
// ---------------------------------------------------------------------------
#define NS 10000
#define NW 30000
#define ND 200
#define DIN 768
#define HC 256
#define PROJ_H 128
#define AS (NW * 4)          // attention-value stride per slot
#define VSZ (DIN * 4)        // V vector stride per slot
#define FEAT_FLOATS (70200 * 256)

// ---------------------------------------------------------------------------
// Scratch (device globals; no allocation allowed)
// ---------------------------------------------------------------------------
__device__ __align__(16) float g_h_sent[NS * DIN];
__device__ __align__(16) float g_h_word[NW * DIN];
__device__ __align__(16) float g_h_doc [ND * DIN];
__device__ __align__(16) float g_feat  [FEAT_FLOATS];
__device__ __align__(16) float g_V     [6 * VSZ];
__device__ __align__(16) float g_als   [6 * AS];
__device__ __align__(16) float g_ald   [6 * AS];
__device__ __align__(16) float g_m     [6 * AS];
__device__ __align__(16) float g_den   [6 * AS];
__device__ __align__(16) float g_ex    [2600000];
__device__ __align__(16) float g_s1    [NS * HC];
__device__ __align__(16) float g_w1    [NW * HC];
__device__ __align__(16) float g_d1    [ND * HC];
__device__ __align__(16) float g_s2    [NS * HC];
__device__ __align__(16) float g_ptmp  [NS * PROJ_H];

// ---------------------------------------------------------------------------
// metadata struct (passed by value)
// ---------------------------------------------------------------------------
struct ConvMeta {
    const int*   ei[6];      // stacked [2,E] edge arrays
    const float* fptr[6];    // per-slot transformed feature base
    float*       out[6];     // scatter accumulators
    int fstride[6];
    int E[6];
    int cumEH[7];
    int cumE[7];
    int srcRows[6];
    int nt, H, C;
};

struct B8 { const float* p[8]; };

// ---------------------------------------------------------------------------
// TF32 tensor-core GEMM v2.
// - tf32 conversion at smem-store time (no cvt in inner loop)
// - A smem k-interleaved: k' = kb*8 + ((k&3)*2 + ((k>>2)&1)) so fragment pairs
//   (k=t, k=t+4) are adjacent -> LDS.64
// - B smem [k][n] padded to 136 words -> conflict-free scalar frag loads
// 128x128 block tile, BK=16, 256 threads (8 warps), warp tile 64x32.
// ---------------------------------------------------------------------------
__device__ __forceinline__ uint32_t f2tf(float x)
{
    uint32_t r;
    asm("cvt.rna.tf32.f32 %0, %1;" : "=r"(r) : "f"(x));
    return r;
}

__device__ __forceinline__ void mma_tf32(float* c, const uint32_t* a, const uint32_t* b)
{
    asm volatile(
        "mma.sync.aligned.m16n8k8.row.col.f32.tf32.tf32.f32 "
        "{%0,%1,%2,%3}, {%4,%5,%6,%7}, {%8,%9}, {%0,%1,%2,%3};"
        : "+f"(c[0]), "+f"(c[1]), "+f"(c[2]), "+f"(c[3])
        : "r"(a[0]), "r"(a[1]), "r"(a[2]), "r"(a[3]), "r"(b[0]), "r"(b[1]));
}

#define TBK 16

__global__ __launch_bounds__(256, 2)
void tgemm(const float* __restrict__ A, B8 bp, const float* __restrict__ bias,
           float* __restrict__ C, int M, int K, int bstride, int ldc, int relu)
{
    __shared__ uint32_t As[128][20];   // [m][k'], tf32
    __shared__ uint32_t Bs[TBK][136];  // [k][n], tf32

    int tid = threadIdx.x;
    int row0 = blockIdx.y * 128;
    int col0 = blockIdx.x * 128;
    const float* B = bp.p[blockIdx.x];

    int lane = tid & 31, warp = tid >> 5;
    int g = lane >> 2, t = lane & 3;
    int wr = warp & 1, wc = warp >> 1;   // 2 warp-rows x 4 warp-cols

    float acc[4][4][4] = {};             // [mt][nt][4]

    int a_r[2], a_c[2], b_r[2], b_c[2];
#pragma unroll
    for (int i = 0; i < 2; i++) {
        int idx = tid + i * 256;
        a_r[i] = idx >> 2;          // 0..127
        a_c[i] = (idx & 3) * 4;     // 0,4,8,12
        b_r[i] = idx >> 5;          // 0..15
        b_c[i] = (idx & 31) * 4;    // 0..124
    }

    const float* Aptr = A + (size_t)row0 * K;

    float4 pa[2], pb[2];
#pragma unroll
    for (int i = 0; i < 2; i++) {
        pa[i] = make_float4(0.f, 0.f, 0.f, 0.f);
        if (row0 + a_r[i] < M) pa[i] = *(const float4*)(Aptr + (size_t)a_r[i] * K + a_c[i]);
        pb[i] = *(const float4*)(B + (size_t)b_r[i] * bstride + b_c[i]);
    }
#pragma unroll
    for (int i = 0; i < 2; i++) {
        int base = (a_c[i] & 8), odd = (a_c[i] & 4) ? 1 : 0;
        As[a_r[i]][base + 0 + odd] = f2tf(pa[i].x);
        As[a_r[i]][base + 2 + odd] = f2tf(pa[i].y);
        As[a_r[i]][base + 4 + odd] = f2tf(pa[i].z);
        As[a_r[i]][base + 6 + odd] = f2tf(pa[i].w);
        uint4 bb = make_uint4(f2tf(pb[i].x), f2tf(pb[i].y), f2tf(pb[i].z), f2tf(pb[i].w));
        *(uint4*)&Bs[b_r[i]][b_c[i]] = bb;
    }
    __syncthreads();

    for (int k0 = TBK; k0 <= K; k0 += TBK) {
        if (k0 < K) {
#pragma unroll
            for (int i = 0; i < 2; i++) {
                pa[i] = make_float4(0.f, 0.f, 0.f, 0.f);
                if (row0 + a_r[i] < M) pa[i] = *(const float4*)(Aptr + (size_t)a_r[i] * K + k0 + a_c[i]);
                pb[i] = *(const float4*)(B + (size_t)(k0 + b_r[i]) * bstride + b_c[i]);
            }
        }
#pragma unroll
        for (int ks = 0; ks < 2; ks++) {
            int kb = ks * 8;
            uint32_t af[4][4], bf[4][2];
#pragma unroll
            for (int mt = 0; mt < 4; mt++) {
                int r = wr * 64 + mt * 16 + g;
                uint2 lo = *(const uint2*)&As[r][kb + 2 * t];
                uint2 hi = *(const uint2*)&As[r + 8][kb + 2 * t];
                af[mt][0] = lo.x; af[mt][1] = hi.x; af[mt][2] = lo.y; af[mt][3] = hi.y;
            }
#pragma unroll
            for (int nt = 0; nt < 4; nt++) {
                int c = wc * 32 + nt * 8 + g;
                bf[nt][0] = Bs[kb + t][c];
                bf[nt][1] = Bs[kb + t + 4][c];
            }
#pragma unroll
            for (int mt = 0; mt < 4; mt++)
#pragma unroll
                for (int nt = 0; nt < 4; nt++)
                    mma_tf32(acc[mt][nt], af[mt], bf[nt]);
        }
        __syncthreads();
        if (k0 < K) {
#pragma unroll
            for (int i = 0; i < 2; i++) {
                int base = (a_c[i] & 8), odd = (a_c[i] & 4) ? 1 : 0;
                As[a_r[i]][base + 0 + odd] = f2tf(pa[i].x);
                As[a_r[i]][base + 2 + odd] = f2tf(pa[i].y);
                As[a_r[i]][base + 4 + odd] = f2tf(pa[i].z);
                As[a_r[i]][base + 6 + odd] = f2tf(pa[i].w);
                uint4 bb = make_uint4(f2tf(pb[i].x), f2tf(pb[i].y), f2tf(pb[i].z), f2tf(pb[i].w));
                *(uint4*)&Bs[b_r[i]][b_c[i]] = bb;
            }
            __syncthreads();
        }
    }

    // epilogue
#pragma unroll
    for (int mt = 0; mt < 4; mt++) {
        int m0 = row0 + wr * 64 + mt * 16 + g;
#pragma unroll
        for (int nt = 0; nt < 4; nt++) {
            int cg = col0 + wc * 32 + nt * 8 + 2 * t;
            float b0 = bias ? bias[cg] : 0.f;
            float b1 = bias ? bias[cg + 1] : 0.f;
            if (m0 < M) {
                float v0 = acc[mt][nt][0] + b0;
                float v1 = acc[mt][nt][1] + b1;
                if (relu) { v0 = fmaxf(v0, 0.f); v1 = fmaxf(v1, 0.f); }
                float* p = C + (size_t)m0 * ldc + cg;
                p[0] = v0; p[1] = v1;
            }
            if (m0 + 8 < M) {
                float v0 = acc[mt][nt][2] + b0;
                float v1 = acc[mt][nt][3] + b1;
                if (relu) { v0 = fmaxf(v0, 0.f); v1 = fmaxf(v1, 0.f); }
                float* p = C + (size_t)(m0 + 8) * ldc + cg;
                p[0] = v0; p[1] = v1;
            }
        }
    }
}

// ---------------------------------------------------------------------------
// build dst-side attention vectors V[slot][k][h] = sum_c Wd[t,k,h*C+c]*ad[t,h,c]
// ---------------------------------------------------------------------------
__global__ void build_vd_all(const float* __restrict__ Wd, const float* __restrict__ ad,
                             float* __restrict__ Vall, int K, int H, int C,
                             int4 tmap)
{
    int slot_t[4] = { tmap.x, tmap.y, tmap.z, tmap.w };
    int slot = blockIdx.y;
    int typ = slot_t[slot & 3];
    if (slot >= 4) typ = (slot == 4) ? 4 : 5;   // conv1 slots 4,5 map to types 4,5
    int idx = blockIdx.x * blockDim.x + threadIdx.x;
    if (idx >= K * H) return;
    int k = idx / H, h = idx - (idx / H) * H;
    const float* w = Wd + (size_t)typ * K * HC + (size_t)k * HC + h * C;
    const float* av = ad + typ * HC + h * C;
    float s = 0.f;
    for (int c = 0; c < C; c++) s += w[c] * av[c];
    Vall[slot * VSZ + k * H + h] = s;
}

// ---------------------------------------------------------------------------
// als[slot][row][h] = sum_c feat[row, h*C+c] * a_s[t, h*C+c]  (warp per (row,h))
// ---------------------------------------------------------------------------
__global__ void als_feat_all(const float* __restrict__ a_s,
                             float* __restrict__ als_all, ConvMeta md, int4 tmap01, int2 tmap2)
{
    int slot = blockIdx.y;
    int typ;
    {
        int tm[6] = { tmap01.x, tmap01.y, tmap01.z, tmap01.w, tmap2.x, tmap2.y };
        typ = tm[slot];
    }
    int id = (blockIdx.x * blockDim.x + threadIdx.x) >> 5;
    int lane = threadIdx.x & 31;
    int H = md.H, C = md.C;
    int rows = md.srcRows[slot];
    if (id >= rows * H) return;
    int row = id / H, h = id - (id / H) * H;
    const float* f = md.fptr[slot] + (size_t)row * md.fstride[slot] + h * C;
    const float* a = a_s + typ * HC + h * C;
    float s = 0.f;
    for (int c = lane; c < C; c += 32) s += f[c] * a[c];
#pragma unroll
    for (int o = 16; o > 0; o >>= 1) s += __shfl_xor_sync(0xffffffffu, s, o);
    if (lane == 0) als_all[slot * AS + row * H + h] = s;
}

// ---------------------------------------------------------------------------
// Grouped ald GEMV: up to 4 slots sharing the same dstX, warp per row.
// ald[slot][row][h] = X[row] . V[slot][:,h]
// ---------------------------------------------------------------------------
__global__ void gemv_ald_group(const float* __restrict__ X, int rows, int K, int H,
                               int4 slots, int ns,
                               const float* __restrict__ Vall, float* __restrict__ ald_all)
{
    int warp = (blockIdx.x * blockDim.x + threadIdx.x) >> 5;
    int lane = threadIdx.x & 31;
    if (warp >= rows) return;
    int sl[4] = { slots.x, slots.y, slots.z, slots.w };
    const float* x = X + (size_t)warp * K;
    float acc[16];
#pragma unroll
    for (int i = 0; i < 16; i++) acc[i] = 0.f;
    for (int k = lane; k < K; k += 32) {
        float xv = x[k];
#pragma unroll
        for (int si = 0; si < 4; si++) {
            if (si >= ns) break;
            const float* v = Vall + sl[si] * VSZ + k * H;
#pragma unroll
            for (int h = 0; h < 4; h++) {
                if (h >= H) break;
                acc[si * 4 + h] += xv * v[h];
            }
        }
    }
#pragma unroll
    for (int i = 0; i < 16; i++)
#pragma unroll
        for (int o = 16; o > 0; o >>= 1)
            acc[i] += __shfl_xor_sync(0xffffffffu, acc[i], o);
    if (lane == 0) {
        for (int si = 0; si < ns; si++)
            for (int h = 0; h < H; h++)
                ald_all[sl[si] * AS + warp * H + h] = acc[si * 4 + h];
    }
}

// ---------------------------------------------------------------------------
// misc
// ---------------------------------------------------------------------------
__global__ void fill_md_kernel(float* __restrict__ m, float* __restrict__ den, int n)
{
    int i = blockIdx.x * blockDim.x + threadIdx.x;
    for (; i < n; i += gridDim.x * blockDim.x) { m[i] = -INFINITY; den[i] = 0.f; }
}

__global__ void init_bias_kernel(float* __restrict__ out, const float* __restrict__ b,
                                 int4 ts, int total)
{
    int i = blockIdx.x * blockDim.x + threadIdx.x;
    for (; i < total; i += gridDim.x * blockDim.x) {
        int c = i & (HC - 1);
        float v = b[ts.x * HC + c];
        if (ts.y >= 0) v += b[ts.y * HC + c];
        if (ts.z >= 0) v += b[ts.z * HC + c];
        if (ts.w >= 0) v += b[ts.w * HC + c];
        out[i] = v;
    }
}

__device__ __forceinline__ void atomicMaxFloat(float* addr, float val)
{
    if (val >= 0.f) atomicMax((int*)addr, __float_as_int(val));
    else            atomicMin((unsigned int*)addr, __float_as_uint(val));
}

// ---------------------------------------------------------------------------
// edge pipeline (batched over all slots)
// ---------------------------------------------------------------------------
__global__ void edge_pass1_all(const float* __restrict__ als_all, const float* __restrict__ ald_all,
                               float* __restrict__ m_all, ConvMeta md)
{
    int idx = blockIdx.x * blockDim.x + threadIdx.x;
    if (idx >= md.cumEH[md.nt]) return;
    int slot = 0;
    while (idx >= md.cumEH[slot + 1]) slot++;
    int local = idx - md.cumEH[slot];
    int H = md.H;
    int e, h;
    if (H == 4) { e = local >> 2; h = local & 3; } else { e = local; h = 0; }
    const int* ei = md.ei[slot];
    int s = ei[e], d = ei[md.E[slot] + e];
    float v = als_all[slot * AS + s * H + h] + ald_all[slot * AS + d * H + h];
    v = (v > 0.f) ? v : 0.2f * v;
    atomicMaxFloat(&m_all[slot * AS + d * H + h], v);
}

__global__ void edge_pass2_all(const float* __restrict__ als_all, const float* __restrict__ ald_all,
                               const float* __restrict__ m_all,
                               float* __restrict__ exbuf, float* __restrict__ den_all, ConvMeta md)
{
    int idx = blockIdx.x * blockDim.x + threadIdx.x;
    if (idx >= md.cumEH[md.nt]) return;
    int slot = 0;
    while (idx >= md.cumEH[slot + 1]) slot++;
    int local = idx - md.cumEH[slot];
    int H = md.H;
    int e, h;
    if (H == 4) { e = local >> 2; h = local & 3; } else { e = local; h = 0; }
    const int* ei = md.ei[slot];
    int s = ei[e], d = ei[md.E[slot] + e];
    float v = als_all[slot * AS + s * H + h] + ald_all[slot * AS + d * H + h];
    v = (v > 0.f) ? v : 0.2f * v;
    float ex = __expf(v - m_all[slot * AS + d * H + h]);
    exbuf[idx] = ex;
    atomicAdd(&den_all[slot * AS + d * H + h], ex);
}

__device__ __forceinline__ void red_add_v4(float* p, float a, float b, float c, float d)
{
    asm volatile("red.global.add.v4.f32 [%0], {%1,%2,%3,%4};"
                 :: "l"(p), "f"(a), "f"(b), "f"(c), "f"(d) : "memory");
}

__global__ void edge_scatter_all(const float* __restrict__ exbuf, const float* __restrict__ den_all,
                                 ConvMeta md)
{
    int wf = (blockIdx.x * blockDim.x + threadIdx.x) >> 5;
    if (wf >= md.cumE[md.nt]) return;
    int lane = threadIdx.x & 31;
    int slot = 0;
    while (wf >= md.cumE[slot + 1]) slot++;
    int e = wf - md.cumE[slot];
    int H = md.H;
    const int* ei = md.ei[slot];
    int s = ei[e], d = ei[md.E[slot] + e];
    const float4* fs = (const float4*)(md.fptr[slot] + (size_t)s * md.fstride[slot]);
    float* od = md.out[slot] + (size_t)d * HC;
    int ebase = md.cumEH[slot] + e * H;
    const float* dslot = den_all + slot * AS + d * H;
#pragma unroll
    for (int j = 0; j < 2; j++) {
        int i4 = lane + j * 32;
        int base = i4 * 4;
        int h = (H == 4) ? (base >> 6) : 0;
        float alpha = exbuf[ebase + h] / (dslot[h] + 1e-16f);
        float4 v = fs[i4];
        red_add_v4(&od[base], v.x * alpha, v.y * alpha, v.z * alpha, v.w * alpha);
    }
}

// ---------------------------------------------------------------------------
// (optional relu) + LayerNorm over last dim D=256, one 256-thread block per row
// ---------------------------------------------------------------------------
__global__ void relu_ln_kernel(const float* __restrict__ in, float* __restrict__ out, int pre_relu)
{
    int n = blockIdx.x;
    int t = threadIdx.x;
    int lane = t & 31, w = t >> 5;
    float v = in[(size_t)n * HC + t];
    if (pre_relu) v = fmaxf(v, 0.f);
    __shared__ float ws[8];
    float s = v;
#pragma unroll
    for (int o = 16; o > 0; o >>= 1) s += __shfl_xor_sync(0xffffffffu, s, o);
    if (lane == 0) ws[w] = s;
    __syncthreads();
    float mu = 0.f;
#pragma unroll
    for (int i = 0; i < 8; i++) mu += ws[i];
    mu *= (1.f / HC);
    __syncthreads();
    float dv = v - mu;
    s = dv * dv;
#pragma unroll
    for (int o = 16; o > 0; o >>= 1) s += __shfl_xor_sync(0xffffffffu, s, o);
    if (lane == 0) ws[w] = s;
    __syncthreads();
    float var = 0.f;
#pragma unroll
    for (int i = 0; i < 8; i++) var += ws[i];
    var *= (1.f / HC);
    out[(size_t)n * HC + t] = dv * rsqrtf(var + 1e-5f);
}

// ---------------------------------------------------------------------------
// host orchestration
// ---------------------------------------------------------------------------
static inline void launch_tgemm(const float* A, const float* B, const float* bias, float* C,
                                int M, int N, int K, int relu)
{
    B8 bp = {};
    int gx = N / 128;
    for (int i = 0; i < gx; i++) bp.p[i] = B + i * 128;
    dim3 grid(gx, (M + 127) / 128);
    tgemm<<<grid, 256>>>(A, bp, bias, C, M, K, N, N, relu);
}

extern "C" void kernel_launch(void* const* d_in, const int* in_sizes, int n_in,
                              void* d_out, int out_size)
{
    const float* x_sent = (const float*)d_in[0];
    const float* x_word = (const float*)d_in[1];
    const float* x_doc  = (const float*)d_in[2];
    const int*   ei[6]  = { (const int*)d_in[3], (const int*)d_in[4], (const int*)d_in[5],
                            (const int*)d_in[6], (const int*)d_in[7], (const int*)d_in[8] };
    int Ecnt[6];
    for (int t = 0; t < 6; t++) Ecnt[t] = in_sizes[3 + t] / 2;
    const float* Wls = (const float*)d_in[9];
    const float* bls = (const float*)d_in[10];
    const float* Wlw = (const float*)d_in[11];
    const float* blw = (const float*)d_in[12];
    const float* Wld = (const float*)d_in[13];
    const float* bld = (const float*)d_in[14];
    const float* W1s = (const float*)d_in[15];
    const float* W1d = (const float*)d_in[16];
    const float* a1s = (const float*)d_in[17];
    const float* a1d = (const float*)d_in[18];
    const float* b1  = (const float*)d_in[19];
    const float* W2s = (const float*)d_in[20];
    const float* W2d = (const float*)d_in[21];
    const float* a2s = (const float*)d_in[22];
    const float* a2d = (const float*)d_in[23];
    const float* b2  = (const float*)d_in[24];
    const float* Wp1 = (const float*)d_in[25];
    const float* bp1 = (const float*)d_in[26];
    const float* Wp2 = (const float*)d_in[27];
    const float* bp2 = (const float*)d_in[28];

    float *h_sent, *h_word, *h_doc, *feat, *Vall, *als, *ald, *m, *den, *exbuf;
    float *s1, *w1, *d1, *s2, *ptmp;
    cudaGetSymbolAddress((void**)&h_sent, g_h_sent);
    cudaGetSymbolAddress((void**)&h_word, g_h_word);
    cudaGetSymbolAddress((void**)&h_doc,  g_h_doc);
    cudaGetSymbolAddress((void**)&feat,   g_feat);
    cudaGetSymbolAddress((void**)&Vall,   g_V);
    cudaGetSymbolAddress((void**)&als,    g_als);
    cudaGetSymbolAddress((void**)&ald,    g_ald);
    cudaGetSymbolAddress((void**)&m,      g_m);
    cudaGetSymbolAddress((void**)&den,    g_den);
    cudaGetSymbolAddress((void**)&exbuf,  g_ex);
    cudaGetSymbolAddress((void**)&s1,     g_s1);
    cudaGetSymbolAddress((void**)&w1,     g_w1);
    cudaGetSymbolAddress((void**)&d1,     g_d1);
    cudaGetSymbolAddress((void**)&s2,     g_s2);
    cudaGetSymbolAddress((void**)&ptmp,   g_ptmp);

    float* out_s2  = (float*)d_out;
    float* out_prj = out_s2 + (size_t)NS * HC;

    // feat sub-buffers
    float* featS = feat;
    float* featW = feat + (size_t)NS * 1024;
    float* featD = featW + (size_t)NW * 256;
    float* featS2 = feat;
    float* featW2 = feat + (size_t)NS * 512;
    float* featD2 = featW2 + (size_t)NW * 256;

    // ---- stage A: input linears + relu ----
    launch_tgemm(x_sent, Wls, bls, h_sent, NS, DIN, DIN, 1);
    launch_tgemm(x_word, Wlw, blw, h_word, NW, DIN, DIN, 1);
    launch_tgemm(x_doc,  Wld, bld, h_doc,  ND, DIN, DIN, 1);

    // ---- conv1 feat GEMMs ----
    {
        B8 bp = {};
        const int st[4] = { 0, 1, 3, 5 };
        for (int i = 0; i < 8; i++)
            bp.p[i] = W1s + (size_t)st[i >> 1] * DIN * HC + (i & 1) * 128;
        tgemm<<<dim3(8, (NS + 127) / 128), 256>>>(h_sent, bp, nullptr, featS, NS, DIN, HC, 1024, 0);
        launch_tgemm(h_word, W1s + 2 * (size_t)DIN * HC, nullptr, featW, NW, HC, DIN, 0);
        launch_tgemm(h_doc,  W1s + 4 * (size_t)DIN * HC, nullptr, featD, ND, HC, DIN, 0);
    }

    // ---- conv1 metadata ----
    ConvMeta m1 = {};
    {
        int          Nsrc1[6] = { NS, NS, NW, NS, ND, NS };
        float*       acc1[6]  = { s1, s1, s1, w1, s1, d1 };
        const float* fp1[6]   = { featS + 0, featS + 256, featW, featS + 512, featD, featS + 768 };
        int          fs1[6]   = { 1024, 1024, 256, 1024, 256, 1024 };
        m1.nt = 6; m1.H = 4; m1.C = 64;
        m1.cumEH[0] = 0; m1.cumE[0] = 0;
        for (int t = 0; t < 6; t++) {
            m1.ei[t] = ei[t];
            m1.fptr[t] = fp1[t];
            m1.fstride[t] = fs1[t];
            m1.out[t] = acc1[t];
            m1.E[t] = Ecnt[t];
            m1.cumEH[t + 1] = m1.cumEH[t] + Ecnt[t] * 4;
            m1.cumE[t + 1] = m1.cumE[t] + Ecnt[t];
            m1.srcRows[t] = Nsrc1[t];
        }
    }

    init_bias_kernel<<<4096, 256>>>(s1, b1, make_int4(0, 1, 2, 4), NS * HC);
    init_bias_kernel<<<4096, 256>>>(w1, b1, make_int4(3, -1, -1, -1), NW * HC);
    init_bias_kernel<<<256,  256>>>(d1, b1, make_int4(5, -1, -1, -1), ND * HC);

    // attention values (fp32)
    build_vd_all<<<dim3((DIN * 4 + 127) / 128, 6), 128>>>(W1d, a1d, Vall, DIN, 4, 64,
                                                          make_int4(0, 1, 2, 3));
    als_feat_all<<<dim3((NW * 4 + 7) / 8, 6), 256>>>(a1s, als, m1,
                                                     make_int4(0, 1, 2, 3), make_int2(4, 5));
    // grouped ald: sent-dst slots {0,1,2,4}; word-dst {3}; doc-dst {5}
    gemv_ald_group<<<(NS * 32 + 255) / 256, 256>>>(h_sent, NS, DIN, 4, make_int4(0, 1, 2, 4), 4, Vall, ald);
    gemv_ald_group<<<(NW * 32 + 255) / 256, 256>>>(h_word, NW, DIN, 4, make_int4(3, 0, 0, 0), 1, Vall, ald);
    gemv_ald_group<<<(ND * 32 + 255) / 256, 256>>>(h_doc,  ND, DIN, 4, make_int4(5, 0, 0, 0), 1, Vall, ald);

    fill_md_kernel<<<2048, 256>>>(m, den, 6 * AS);
    {
        int tot = m1.cumEH[6];
        edge_pass1_all<<<(tot + 255) / 256, 256>>>(als, ald, m, m1);
        edge_pass2_all<<<(tot + 255) / 256, 256>>>(als, ald, m, exbuf, den, m1);
        int totw = m1.cumE[6];
        edge_scatter_all<<<(totw * 32 + 255) / 256, 256>>>(exbuf, den, m1);
    }

    // ---- relu + LN ----
    relu_ln_kernel<<<NS, HC>>>(s1, s1, 1);
    relu_ln_kernel<<<NW, HC>>>(w1, w1, 1);
    relu_ln_kernel<<<ND, HC>>>(d1, d1, 1);

    // ---- conv2 feat GEMMs ----
    {
        B8 bp = {};
        const int st[2] = { 0, 1 };
        for (int i = 0; i < 4; i++)
            bp.p[i] = W2s + (size_t)st[i >> 1] * HC * HC + (i & 1) * 128;
        tgemm<<<dim3(4, (NS + 127) / 128), 256>>>(s1, bp, nullptr, featS2, NS, HC, HC, 512, 0);
        launch_tgemm(w1, W2s + 2 * (size_t)HC * HC, nullptr, featW2, NW, HC, HC, 0);
        launch_tgemm(d1, W2s + 4 * (size_t)HC * HC, nullptr, featD2, ND, HC, HC, 0);
    }

    // ---- conv2 metadata (types {0,1,2,4} -> sentences) ----
    ConvMeta m2 = {};
    {
        const int    t2[4]    = { 0, 1, 2, 4 };
        int          Nsrc2[4] = { NS, NS, NW, ND };
        const float* fp2[4]   = { featS2 + 0, featS2 + 256, featW2, featD2 };
        int          fs2[4]   = { 512, 512, 256, 256 };
        m2.nt = 4; m2.H = 1; m2.C = 256;
        m2.cumEH[0] = 0; m2.cumE[0] = 0;
        for (int i = 0; i < 4; i++) {
            m2.ei[i] = ei[t2[i]];
            m2.fptr[i] = fp2[i];
            m2.fstride[i] = fs2[i];
            m2.out[i] = s2;
            m2.E[i] = Ecnt[t2[i]];
            m2.cumEH[i + 1] = m2.cumEH[i] + Ecnt[t2[i]];
            m2.cumE[i + 1] = m2.cumE[i] + Ecnt[t2[i]];
            m2.srcRows[i] = Nsrc2[i];
        }
    }

    init_bias_kernel<<<4096, 256>>>(s2, b2, make_int4(0, 1, 2, 4), NS * HC);

    build_vd_all<<<dim3((HC * 1 + 127) / 128, 4), 128>>>(W2d, a2d, Vall, HC, 1, 256,
                                                         make_int4(0, 1, 2, 4));
    als_feat_all<<<dim3((NW * 1 + 7) / 8, 4), 256>>>(a2s, als, m2,
                                                     make_int4(0, 1, 2, 4), make_int2(0, 0));
    // all conv2 dst = s1 (slots 0..3)
    gemv_ald_group<<<(NS * 32 + 255) / 256, 256>>>(s1, NS, HC, 1, make_int4(0, 1, 2, 3), 4, Vall, ald);

    fill_md_kernel<<<2048, 256>>>(m, den, 6 * AS);
    {
        int tot = m2.cumEH[4];
        edge_pass1_all<<<(tot + 255) / 256, 256>>>(als, ald, m, m2);
        edge_pass2_all<<<(tot + 255) / 256, 256>>>(als, ald, m, exbuf, den, m2);
        int totw = m2.cumE[4];
        edge_scatter_all<<<(totw * 32 + 255) / 256, 256>>>(exbuf, den, m2);
    }

    // ---- final LN (no relu) -> output s2 ----
    relu_ln_kernel<<<NS, HC>>>(s2, out_s2, 0);

    // ---- projection head ----
    if (out_size >= NS * (HC + PROJ_H)) {
        launch_tgemm(out_s2, Wp1, bp1, ptmp, NS, PROJ_H, HC, 1);
        launch_tgemm(ptmp, Wp2, bp2, out_prj, NS, PROJ_H, PROJ_H, 0);
    }
}

// round 8
// speedup vs baseline: 3.1646x; 1.0637x over previous
#include <cuda_runtime.h>
#include <cstdint>
#include <math.h>

// ---------------------------------------------------------------------------
// Problem constants
// ---------------------------------------------------------------------------
#define NS 10000
#define NW 30000
#define ND 200
#define DIN 768
#define HC 256
#define PROJ_H 128
#define AS (NW * 4)          // attention-value stride per slot
#define VSZ (DIN * 4)        // V vector stride per slot
#define FEAT_FLOATS (70200 * 256)

// ---------------------------------------------------------------------------
// Scratch (device globals; no allocation allowed)
// ---------------------------------------------------------------------------
__device__ __align__(16) float g_h_sent[NS * DIN];
__device__ __align__(16) float g_h_word[NW * DIN];
__device__ __align__(16) float g_h_doc [ND * DIN];
__device__ __align__(16) float g_feat  [FEAT_FLOATS];
__device__ __align__(16) float g_V     [6 * VSZ];
__device__ __align__(16) float g_als   [6 * AS];
__device__ __align__(16) float g_ald   [6 * AS];
__device__ __align__(16) float g_m     [6 * AS];
__device__ __align__(16) float g_den   [6 * AS];
__device__ __align__(16) float g_ex    [2600000];
__device__ __align__(16) float g_s1    [NS * HC];
__device__ __align__(16) float g_w1    [NW * HC];
__device__ __align__(16) float g_d1    [ND * HC];
__device__ __align__(16) float g_s2    [NS * HC];
__device__ __align__(16) float g_ptmp  [NS * PROJ_H];

// ---------------------------------------------------------------------------
// metadata struct (passed by value)
// ---------------------------------------------------------------------------
struct ConvMeta {
    const int*   ei[6];      // stacked [2,E] edge arrays
    const float* fptr[6];    // per-slot transformed feature base
    float*       out[6];     // scatter accumulators
    int fstride[6];
    int E[6];
    int cumEH[7];
    int cumE[7];
    int srcRows[6];
    int nt, H, C;
};

struct B8 { const float* p[8]; };

// ---------------------------------------------------------------------------
// TF32 tensor-core GEMM v3: cp.async 2-stage pipeline.
// - global->smem via cp.async (no register staging), one sync per k-tile
// - fp32 in smem; cvt.rna.tf32 in fragment-load path (R4 layout, the fast one)
// 128x128 block tile, BK=16, 256 threads (8 warps), warp tile 64x32,
// mma.sync.aligned.m16n8k8.row.col.f32.tf32.tf32.f32.
// ---------------------------------------------------------------------------
__device__ __forceinline__ uint32_t f2tf(float x)
{
    uint32_t r;
    asm("cvt.rna.tf32.f32 %0, %1;" : "=r"(r) : "f"(x));
    return r;
}

__device__ __forceinline__ void mma_tf32(float* c, const uint32_t* a, const uint32_t* b)
{
    asm volatile(
        "mma.sync.aligned.m16n8k8.row.col.f32.tf32.tf32.f32 "
        "{%0,%1,%2,%3}, {%4,%5,%6,%7}, {%8,%9}, {%0,%1,%2,%3};"
        : "+f"(c[0]), "+f"(c[1]), "+f"(c[2]), "+f"(c[3])
        : "r"(a[0]), "r"(a[1]), "r"(a[2]), "r"(a[3]), "r"(b[0]), "r"(b[1]));
}

__device__ __forceinline__ void cp16(uint32_t saddr, const void* gptr, int bytes)
{
    asm volatile("cp.async.cg.shared.global [%0], [%1], 16, %2;"
                 :: "r"(saddr), "l"(gptr), "r"(bytes));
}

#define TBK 16

__global__ __launch_bounds__(256, 2)
void tgemm(const float* __restrict__ A, B8 bp, const float* __restrict__ bias,
           float* __restrict__ C, int M, int K, int bstride, int ldc, int relu)
{
    __shared__ float As[2][128][20];   // [stage][m][k]
    __shared__ float Bs[2][TBK][132];  // [stage][k][n]

    int tid = threadIdx.x;
    int row0 = blockIdx.y * 128;
    int col0 = blockIdx.x * 128;
    const float* B = bp.p[blockIdx.x];

    int lane = tid & 31, warp = tid >> 5;
    int g = lane >> 2, t = lane & 3;
    int wr = warp & 1, wc = warp >> 1;   // 2 warp-rows x 4 warp-cols

    float acc[4][4][4] = {};             // [mt][nt][4]

    int a_r[2], a_c[2], b_r[2], b_c[2];
    uint32_t sa[2][2], sb[2][2];         // smem dst addresses per stage
#pragma unroll
    for (int i = 0; i < 2; i++) {
        int idx = tid + i * 256;
        a_r[i] = idx >> 2;          // 0..127
        a_c[i] = (idx & 3) * 4;     // 0,4,8,12
        b_r[i] = idx >> 5;          // 0..15
        b_c[i] = (idx & 31) * 4;    // 0..124
#pragma unroll
        for (int s = 0; s < 2; s++) {
            sa[s][i] = (uint32_t)__cvta_generic_to_shared(&As[s][a_r[i]][a_c[i]]);
            sb[s][i] = (uint32_t)__cvta_generic_to_shared(&Bs[s][b_r[i]][b_c[i]]);
        }
    }

    const float* Aptr = A + (size_t)row0 * K;
    int a_ok[2];
#pragma unroll
    for (int i = 0; i < 2; i++) a_ok[i] = (row0 + a_r[i] < M) ? 16 : 0;

    // prologue: issue tile 0 into stage 0
#pragma unroll
    for (int i = 0; i < 2; i++) {
        cp16(sa[0][i], Aptr + (size_t)a_r[i] * K + a_c[i], a_ok[i]);
        cp16(sb[0][i], B + (size_t)b_r[i] * bstride + b_c[i], 16);
    }
    asm volatile("cp.async.commit_group;");

    int ntile = K / TBK;
    for (int kt = 0; kt < ntile; kt++) {
        asm volatile("cp.async.wait_group 0;");
        __syncthreads();
        // issue next tile (overlaps compute below)
        if (kt + 1 < ntile) {
            int k0 = (kt + 1) * TBK;
            int s = (kt + 1) & 1;
#pragma unroll
            for (int i = 0; i < 2; i++) {
                cp16(sa[s][i], Aptr + (size_t)a_r[i] * K + k0 + a_c[i], a_ok[i]);
                cp16(sb[s][i], B + (size_t)(k0 + b_r[i]) * bstride + b_c[i], 16);
            }
        }
        asm volatile("cp.async.commit_group;");
        int s = kt & 1;
#pragma unroll
        for (int ks = 0; ks < 2; ks++) {
            int kb = ks * 8;
            uint32_t af[4][4], bf[4][2];
#pragma unroll
            for (int mt = 0; mt < 4; mt++) {
                int r = wr * 64 + mt * 16 + g;
                af[mt][0] = f2tf(As[s][r][kb + t]);
                af[mt][1] = f2tf(As[s][r + 8][kb + t]);
                af[mt][2] = f2tf(As[s][r][kb + t + 4]);
                af[mt][3] = f2tf(As[s][r + 8][kb + t + 4]);
            }
#pragma unroll
            for (int nt4 = 0; nt4 < 4; nt4++) {
                int c = wc * 32 + nt4 * 8 + g;
                bf[nt4][0] = f2tf(Bs[s][kb + t][c]);
                bf[nt4][1] = f2tf(Bs[s][kb + t + 4][c]);
            }
#pragma unroll
            for (int mt = 0; mt < 4; mt++)
#pragma unroll
                for (int nt4 = 0; nt4 < 4; nt4++)
                    mma_tf32(acc[mt][nt4], af[mt], bf[nt4]);
        }
        __syncthreads();
    }

    // epilogue
#pragma unroll
    for (int mt = 0; mt < 4; mt++) {
        int m0 = row0 + wr * 64 + mt * 16 + g;
#pragma unroll
        for (int nt4 = 0; nt4 < 4; nt4++) {
            int cg = col0 + wc * 32 + nt4 * 8 + 2 * t;
            float b0 = bias ? bias[cg] : 0.f;
            float b1 = bias ? bias[cg + 1] : 0.f;
            if (m0 < M) {
                float v0 = acc[mt][nt4][0] + b0;
                float v1 = acc[mt][nt4][1] + b1;
                if (relu) { v0 = fmaxf(v0, 0.f); v1 = fmaxf(v1, 0.f); }
                float* p = C + (size_t)m0 * ldc + cg;
                p[0] = v0; p[1] = v1;
            }
            if (m0 + 8 < M) {
                float v0 = acc[mt][nt4][2] + b0;
                float v1 = acc[mt][nt4][3] + b1;
                if (relu) { v0 = fmaxf(v0, 0.f); v1 = fmaxf(v1, 0.f); }
                float* p = C + (size_t)(m0 + 8) * ldc + cg;
                p[0] = v0; p[1] = v1;
            }
        }
    }
}

// ---------------------------------------------------------------------------
// build dst-side attention vectors V[slot][k][h] = sum_c Wd[t,k,h*C+c]*ad[t,h,c]
// ---------------------------------------------------------------------------
__global__ void build_vd_all(const float* __restrict__ Wd, const float* __restrict__ ad,
                             float* __restrict__ Vall, int K, int H, int C,
                             int4 tmap)
{
    int slot_t[4] = { tmap.x, tmap.y, tmap.z, tmap.w };
    int slot = blockIdx.y;
    int typ = slot_t[slot & 3];
    if (slot >= 4) typ = (slot == 4) ? 4 : 5;   // conv1 slots 4,5 map to types 4,5
    int idx = blockIdx.x * blockDim.x + threadIdx.x;
    if (idx >= K * H) return;
    int k = idx / H, h = idx - (idx / H) * H;
    const float* w = Wd + (size_t)typ * K * HC + (size_t)k * HC + h * C;
    const float* av = ad + typ * HC + h * C;
    float s = 0.f;
    for (int c = 0; c < C; c++) s += w[c] * av[c];
    Vall[slot * VSZ + k * H + h] = s;
}

// ---------------------------------------------------------------------------
// als[slot][row][h] = sum_c feat[row, h*C+c] * a_s[t, h*C+c]  (warp per (row,h))
// ---------------------------------------------------------------------------
__global__ void als_feat_all(const float* __restrict__ a_s,
                             float* __restrict__ als_all, ConvMeta md, int4 tmap01, int2 tmap2)
{
    int slot = blockIdx.y;
    int typ;
    {
        int tm[6] = { tmap01.x, tmap01.y, tmap01.z, tmap01.w, tmap2.x, tmap2.y };
        typ = tm[slot];
    }
    int id = (blockIdx.x * blockDim.x + threadIdx.x) >> 5;
    int lane = threadIdx.x & 31;
    int H = md.H, C = md.C;
    int rows = md.srcRows[slot];
    if (id >= rows * H) return;
    int row = id / H, h = id - (id / H) * H;
    const float* f = md.fptr[slot] + (size_t)row * md.fstride[slot] + h * C;
    const float* a = a_s + typ * HC + h * C;
    float s = 0.f;
    for (int c = lane; c < C; c += 32) s += f[c] * a[c];
#pragma unroll
    for (int o = 16; o > 0; o >>= 1) s += __shfl_xor_sync(0xffffffffu, s, o);
    if (lane == 0) als_all[slot * AS + row * H + h] = s;
}

// ---------------------------------------------------------------------------
// Grouped ald GEMV: up to 4 slots sharing the same dstX, warp per row.
// ---------------------------------------------------------------------------
__global__ void gemv_ald_group(const float* __restrict__ X, int rows, int K, int H,
                               int4 slots, int ns,
                               const float* __restrict__ Vall, float* __restrict__ ald_all)
{
    int warp = (blockIdx.x * blockDim.x + threadIdx.x) >> 5;
    int lane = threadIdx.x & 31;
    if (warp >= rows) return;
    int sl[4] = { slots.x, slots.y, slots.z, slots.w };
    const float* x = X + (size_t)warp * K;
    float acc[16];
#pragma unroll
    for (int i = 0; i < 16; i++) acc[i] = 0.f;
    for (int k = lane; k < K; k += 32) {
        float xv = x[k];
#pragma unroll
        for (int si = 0; si < 4; si++) {
            if (si >= ns) break;
            const float* v = Vall + sl[si] * VSZ + k * H;
#pragma unroll
            for (int h = 0; h < 4; h++) {
                if (h >= H) break;
                acc[si * 4 + h] += xv * v[h];
            }
        }
    }
#pragma unroll
    for (int i = 0; i < 16; i++)
#pragma unroll
        for (int o = 16; o > 0; o >>= 1)
            acc[i] += __shfl_xor_sync(0xffffffffu, acc[i], o);
    if (lane == 0) {
        for (int si = 0; si < ns; si++)
            for (int h = 0; h < H; h++)
                ald_all[sl[si] * AS + warp * H + h] = acc[si * 4 + h];
    }
}

// ---------------------------------------------------------------------------
// misc
// ---------------------------------------------------------------------------
__global__ void fill_md_kernel(float* __restrict__ m, float* __restrict__ den, int n)
{
    int i = blockIdx.x * blockDim.x + threadIdx.x;
    for (; i < n; i += gridDim.x * blockDim.x) { m[i] = -INFINITY; den[i] = 0.f; }
}

__global__ void init_bias_kernel(float* __restrict__ out, const float* __restrict__ b,
                                 int4 ts, int total)
{
    int i = blockIdx.x * blockDim.x + threadIdx.x;
    for (; i < total; i += gridDim.x * blockDim.x) {
        int c = i & (HC - 1);
        float v = b[ts.x * HC + c];
        if (ts.y >= 0) v += b[ts.y * HC + c];
        if (ts.z >= 0) v += b[ts.z * HC + c];
        if (ts.w >= 0) v += b[ts.w * HC + c];
        out[i] = v;
    }
}

__device__ __forceinline__ void atomicMaxFloat(float* addr, float val)
{
    if (val >= 0.f) atomicMax((int*)addr, __float_as_int(val));
    else            atomicMin((unsigned int*)addr, __float_as_uint(val));
}

// ---------------------------------------------------------------------------
// edge pipeline (batched over all slots)
// ---------------------------------------------------------------------------
__global__ void edge_pass1_all(const float* __restrict__ als_all, const float* __restrict__ ald_all,
                               float* __restrict__ m_all, ConvMeta md)
{
    int idx = blockIdx.x * blockDim.x + threadIdx.x;
    if (idx >= md.cumEH[md.nt]) return;
    int slot = 0;
    while (idx >= md.cumEH[slot + 1]) slot++;
    int local = idx - md.cumEH[slot];
    int H = md.H;
    int e, h;
    if (H == 4) { e = local >> 2; h = local & 3; } else { e = local; h = 0; }
    const int* ei = md.ei[slot];
    int s = ei[e], d = ei[md.E[slot] + e];
    float v = als_all[slot * AS + s * H + h] + ald_all[slot * AS + d * H + h];
    v = (v > 0.f) ? v : 0.2f * v;
    atomicMaxFloat(&m_all[slot * AS + d * H + h], v);
}

__global__ void edge_pass2_all(const float* __restrict__ als_all, const float* __restrict__ ald_all,
                               const float* __restrict__ m_all,
                               float* __restrict__ exbuf, float* __restrict__ den_all, ConvMeta md)
{
    int idx = blockIdx.x * blockDim.x + threadIdx.x;
    if (idx >= md.cumEH[md.nt]) return;
    int slot = 0;
    while (idx >= md.cumEH[slot + 1]) slot++;
    int local = idx - md.cumEH[slot];
    int H = md.H;
    int e, h;
    if (H == 4) { e = local >> 2; h = local & 3; } else { e = local; h = 0; }
    const int* ei = md.ei[slot];
    int s = ei[e], d = ei[md.E[slot] + e];
    float v = als_all[slot * AS + s * H + h] + ald_all[slot * AS + d * H + h];
    v = (v > 0.f) ? v : 0.2f * v;
    float ex = __expf(v - m_all[slot * AS + d * H + h]);
    exbuf[idx] = ex;
    atomicAdd(&den_all[slot * AS + d * H + h], ex);
}

__device__ __forceinline__ void red_add_v4(float* p, float a, float b, float c, float d)
{
    asm volatile("red.global.add.v4.f32 [%0], {%1,%2,%3,%4};"
                 :: "l"(p), "f"(a), "f"(b), "f"(c), "f"(d) : "memory");
}

__global__ void edge_scatter_all(const float* __restrict__ exbuf, const float* __restrict__ den_all,
                                 ConvMeta md)
{
    int wf = (blockIdx.x * blockDim.x + threadIdx.x) >> 5;
    if (wf >= md.cumE[md.nt]) return;
    int lane = threadIdx.x & 31;
    int slot = 0;
    while (wf >= md.cumE[slot + 1]) slot++;
    int e = wf - md.cumE[slot];
    int H = md.H;
    const int* ei = md.ei[slot];
    int s = ei[e], d = ei[md.E[slot] + e];
    const float4* fs = (const float4*)(md.fptr[slot] + (size_t)s * md.fstride[slot]);
    float* od = md.out[slot] + (size_t)d * HC;
    int ebase = md.cumEH[slot] + e * H;
    const float* dslot = den_all + slot * AS + d * H;
#pragma unroll
    for (int j = 0; j < 2; j++) {
        int i4 = lane + j * 32;
        int base = i4 * 4;
        int h = (H == 4) ? (base >> 6) : 0;
        float alpha = exbuf[ebase + h] / (dslot[h] + 1e-16f);
        float4 v = fs[i4];
        red_add_v4(&od[base], v.x * alpha, v.y * alpha, v.z * alpha, v.w * alpha);
    }
}

// ---------------------------------------------------------------------------
// (optional relu) + LayerNorm over last dim D=256, one 256-thread block per row
// ---------------------------------------------------------------------------
__global__ void relu_ln_kernel(const float* __restrict__ in, float* __restrict__ out, int pre_relu)
{
    int n = blockIdx.x;
    int t = threadIdx.x;
    int lane = t & 31, w = t >> 5;
    float v = in[(size_t)n * HC + t];
    if (pre_relu) v = fmaxf(v, 0.f);
    __shared__ float ws[8];
    float s = v;
#pragma unroll
    for (int o = 16; o > 0; o >>= 1) s += __shfl_xor_sync(0xffffffffu, s, o);
    if (lane == 0) ws[w] = s;
    __syncthreads();
    float mu = 0.f;
#pragma unroll
    for (int i = 0; i < 8; i++) mu += ws[i];
    mu *= (1.f / HC);
    __syncthreads();
    float dv = v - mu;
    s = dv * dv;
#pragma unroll
    for (int o = 16; o > 0; o >>= 1) s += __shfl_xor_sync(0xffffffffu, s, o);
    if (lane == 0) ws[w] = s;
    __syncthreads();
    float var = 0.f;
#pragma unroll
    for (int i = 0; i < 8; i++) var += ws[i];
    var *= (1.f / HC);
    out[(size_t)n * HC + t] = dv * rsqrtf(var + 1e-5f);
}

// ---------------------------------------------------------------------------
// host orchestration
// ---------------------------------------------------------------------------
static inline void launch_tgemm(const float* A, const float* B, const float* bias, float* C,
                                int M, int N, int K, int relu)
{
    B8 bp = {};
    int gx = N / 128;
    for (int i = 0; i < gx; i++) bp.p[i] = B + i * 128;
    dim3 grid(gx, (M + 127) / 128);
    tgemm<<<grid, 256>>>(A, bp, bias, C, M, K, N, N, relu);
}

extern "C" void kernel_launch(void* const* d_in, const int* in_sizes, int n_in,
                              void* d_out, int out_size)
{
    const float* x_sent = (const float*)d_in[0];
    const float* x_word = (const float*)d_in[1];
    const float* x_doc  = (const float*)d_in[2];
    const int*   ei[6]  = { (const int*)d_in[3], (const int*)d_in[4], (const int*)d_in[5],
                            (const int*)d_in[6], (const int*)d_in[7], (const int*)d_in[8] };
    int Ecnt[6];
    for (int t = 0; t < 6; t++) Ecnt[t] = in_sizes[3 + t] / 2;
    const float* Wls = (const float*)d_in[9];
    const float* bls = (const float*)d_in[10];
    const float* Wlw = (const float*)d_in[11];
    const float* blw = (const float*)d_in[12];
    const float* Wld = (const float*)d_in[13];
    const float* bld = (const float*)d_in[14];
    const float* W1s = (const float*)d_in[15];
    const float* W1d = (const float*)d_in[16];
    const float* a1s = (const float*)d_in[17];
    const float* a1d = (const float*)d_in[18];
    const float* b1  = (const float*)d_in[19];
    const float* W2s = (const float*)d_in[20];
    const float* W2d = (const float*)d_in[21];
    const float* a2s = (const float*)d_in[22];
    const float* a2d = (const float*)d_in[23];
    const float* b2  = (const float*)d_in[24];
    const float* Wp1 = (const float*)d_in[25];
    const float* bp1 = (const float*)d_in[26];
    const float* Wp2 = (const float*)d_in[27];
    const float* bp2 = (const float*)d_in[28];

    float *h_sent, *h_word, *h_doc, *feat, *Vall, *als, *ald, *m, *den, *exbuf;
    float *s1, *w1, *d1, *s2, *ptmp;
    cudaGetSymbolAddress((void**)&h_sent, g_h_sent);
    cudaGetSymbolAddress((void**)&h_word, g_h_word);
    cudaGetSymbolAddress((void**)&h_doc,  g_h_doc);
    cudaGetSymbolAddress((void**)&feat,   g_feat);
    cudaGetSymbolAddress((void**)&Vall,   g_V);
    cudaGetSymbolAddress((void**)&als,    g_als);
    cudaGetSymbolAddress((void**)&ald,    g_ald);
    cudaGetSymbolAddress((void**)&m,      g_m);
    cudaGetSymbolAddress((void**)&den,    g_den);
    cudaGetSymbolAddress((void**)&exbuf,  g_ex);
    cudaGetSymbolAddress((void**)&s1,     g_s1);
    cudaGetSymbolAddress((void**)&w1,     g_w1);
    cudaGetSymbolAddress((void**)&d1,     g_d1);
    cudaGetSymbolAddress((void**)&s2,     g_s2);
    cudaGetSymbolAddress((void**)&ptmp,   g_ptmp);

    float* out_s2  = (float*)d_out;
    float* out_prj = out_s2 + (size_t)NS * HC;

    // feat sub-buffers
    float* featS = feat;
    float* featW = feat + (size_t)NS * 1024;
    float* featD = featW + (size_t)NW * 256;
    float* featS2 = feat;
    float* featW2 = feat + (size_t)NS * 512;
    float* featD2 = featW2 + (size_t)NW * 256;

    // ---- stage A: input linears + relu ----
    launch_tgemm(x_sent, Wls, bls, h_sent, NS, DIN, DIN, 1);
    launch_tgemm(x_word, Wlw, blw, h_word, NW, DIN, DIN, 1);
    launch_tgemm(x_doc,  Wld, bld, h_doc,  ND, DIN, DIN, 1);

    // ---- conv1 feat GEMMs ----
    {
        B8 bp = {};
        const int st[4] = { 0, 1, 3, 5 };
        for (int i = 0; i < 8; i++)
            bp.p[i] = W1s + (size_t)st[i >> 1] * DIN * HC + (i & 1) * 128;
        tgemm<<<dim3(8, (NS + 127) / 128), 256>>>(h_sent, bp, nullptr, featS, NS, DIN, HC, 1024, 0);
        launch_tgemm(h_word, W1s + 2 * (size_t)DIN * HC, nullptr, featW, NW, HC, DIN, 0);
        launch_tgemm(h_doc,  W1s + 4 * (size_t)DIN * HC, nullptr, featD, ND, HC, DIN, 0);
    }

    // ---- conv1 metadata ----
    ConvMeta m1 = {};
    {
        int          Nsrc1[6] = { NS, NS, NW, NS, ND, NS };
        float*       acc1[6]  = { s1, s1, s1, w1, s1, d1 };
        const float* fp1[6]   = { featS + 0, featS + 256, featW, featS + 512, featD, featS + 768 };
        int          fs1[6]   = { 1024, 1024, 256, 1024, 256, 1024 };
        m1.nt = 6; m1.H = 4; m1.C = 64;
        m1.cumEH[0] = 0; m1.cumE[0] = 0;
        for (int t = 0; t < 6; t++) {
            m1.ei[t] = ei[t];
            m1.fptr[t] = fp1[t];
            m1.fstride[t] = fs1[t];
            m1.out[t] = acc1[t];
            m1.E[t] = Ecnt[t];
            m1.cumEH[t + 1] = m1.cumEH[t] + Ecnt[t] * 4;
            m1.cumE[t + 1] = m1.cumE[t] + Ecnt[t];
            m1.srcRows[t] = Nsrc1[t];
        }
    }

    init_bias_kernel<<<4096, 256>>>(s1, b1, make_int4(0, 1, 2, 4), NS * HC);
    init_bias_kernel<<<4096, 256>>>(w1, b1, make_int4(3, -1, -1, -1), NW * HC);
    init_bias_kernel<<<256,  256>>>(d1, b1, make_int4(5, -1, -1, -1), ND * HC);

    // attention values (fp32)
    build_vd_all<<<dim3((DIN * 4 + 127) / 128, 6), 128>>>(W1d, a1d, Vall, DIN, 4, 64,
                                                          make_int4(0, 1, 2, 3));
    als_feat_all<<<dim3((NW * 4 + 7) / 8, 6), 256>>>(a1s, als, m1,
                                                     make_int4(0, 1, 2, 3), make_int2(4, 5));
    gemv_ald_group<<<(NS * 32 + 255) / 256, 256>>>(h_sent, NS, DIN, 4, make_int4(0, 1, 2, 4), 4, Vall, ald);
    gemv_ald_group<<<(NW * 32 + 255) / 256, 256>>>(h_word, NW, DIN, 4, make_int4(3, 0, 0, 0), 1, Vall, ald);
    gemv_ald_group<<<(ND * 32 + 255) / 256, 256>>>(h_doc,  ND, DIN, 4, make_int4(5, 0, 0, 0), 1, Vall, ald);

    fill_md_kernel<<<2048, 256>>>(m, den, 6 * AS);
    {
        int tot = m1.cumEH[6];
        edge_pass1_all<<<(tot + 255) / 256, 256>>>(als, ald, m, m1);
        edge_pass2_all<<<(tot + 255) / 256, 256>>>(als, ald, m, exbuf, den, m1);
        int totw = m1.cumE[6];
        edge_scatter_all<<<(totw * 32 + 255) / 256, 256>>>(exbuf, den, m1);
    }

    // ---- relu + LN ----
    relu_ln_kernel<<<NS, HC>>>(s1, s1, 1);
    relu_ln_kernel<<<NW, HC>>>(w1, w1, 1);
    relu_ln_kernel<<<ND, HC>>>(d1, d1, 1);

    // ---- conv2 feat GEMMs ----
    {
        B8 bp = {};
        const int st[2] = { 0, 1 };
        for (int i = 0; i < 4; i++)
            bp.p[i] = W2s + (size_t)st[i >> 1] * HC * HC + (i & 1) * 128;
        tgemm<<<dim3(4, (NS + 127) / 128), 256>>>(s1, bp, nullptr, featS2, NS, HC, HC, 512, 0);
        launch_tgemm(w1, W2s + 2 * (size_t)HC * HC, nullptr, featW2, NW, HC, HC, 0);
        launch_tgemm(d1, W2s + 4 * (size_t)HC * HC, nullptr, featD2, ND, HC, HC, 0);
    }

    // ---- conv2 metadata (types {0,1,2,4} -> sentences) ----
    ConvMeta m2 = {};
    {
        const int    t2[4]    = { 0, 1, 2, 4 };
        int          Nsrc2[4] = { NS, NS, NW, ND };
        const float* fp2[4]   = { featS2 + 0, featS2 + 256, featW2, featD2 };
        int          fs2[4]   = { 512, 512, 256, 256 };
        m2.nt = 4; m2.H = 1; m2.C = 256;
        m2.cumEH[0] = 0; m2.cumE[0] = 0;
        for (int i = 0; i < 4; i++) {
            m2.ei[i] = ei[t2[i]];
            m2.fptr[i] = fp2[i];
            m2.fstride[i] = fs2[i];
            m2.out[i] = s2;
            m2.E[i] = Ecnt[t2[i]];
            m2.cumEH[i + 1] = m2.cumEH[i] + Ecnt[t2[i]];
            m2.cumE[i + 1] = m2.cumE[i] + Ecnt[t2[i]];
            m2.srcRows[i] = Nsrc2[i];
        }
    }

    init_bias_kernel<<<4096, 256>>>(s2, b2, make_int4(0, 1, 2, 4), NS * HC);

    build_vd_all<<<dim3((HC * 1 + 127) / 128, 4), 128>>>(W2d, a2d, Vall, HC, 1, 256,
                                                         make_int4(0, 1, 2, 4));
    als_feat_all<<<dim3((NW * 1 + 7) / 8, 4), 256>>>(a2s, als, m2,
                                                     make_int4(0, 1, 2, 4), make_int2(0, 0));
    gemv_ald_group<<<(NS * 32 + 255) / 256, 256>>>(s1, NS, HC, 1, make_int4(0, 1, 2, 3), 4, Vall, ald);

    fill_md_kernel<<<2048, 256>>>(m, den, 6 * AS);
    {
        int tot = m2.cumEH[4];
        edge_pass1_all<<<(tot + 255) / 256, 256>>>(als, ald, m, m2);
        edge_pass2_all<<<(tot + 255) / 256, 256>>>(als, ald, m, exbuf, den, m2);
        int totw = m2.cumE[4];
        edge_scatter_all<<<(totw * 32 + 255) / 256, 256>>>(exbuf, den, m2);
    }

    // ---- final LN (no relu) -> output s2 ----
    relu_ln_kernel<<<NS, HC>>>(s2, out_s2, 0);

    // ---- projection head ----
    if (out_size >= NS * (HC + PROJ_H)) {
        launch_tgemm(out_s2, Wp1, bp1, ptmp, NS, PROJ_H, HC, 1);
        launch_tgemm(ptmp, Wp2, bp2, out_prj, NS, PROJ_H, PROJ_H, 0);
    }
}

// round 9
// speedup vs baseline: 3.2634x; 1.0312x over previous
#include <cuda_runtime.h>
#include <cstdint>
#include <math.h>

// ---------------------------------------------------------------------------
// Problem constants
// ---------------------------------------------------------------------------
#define NS 10000
#define NW 30000
#define ND 200
#define DIN 768
#define HC 256
#define PROJ_H 128
#define AS (NW * 4)          // attention-value stride per slot
#define VSZ (DIN * 4)        // V vector stride per slot
#define FEAT_FLOATS (70200 * 256)

// ---------------------------------------------------------------------------
// Scratch (device globals; no allocation allowed)
// ---------------------------------------------------------------------------
__device__ __align__(16) float g_h_sent[NS * DIN];
__device__ __align__(16) float g_h_word[NW * DIN];
__device__ __align__(16) float g_h_doc [ND * DIN];
__device__ __align__(16) float g_feat  [FEAT_FLOATS];
__device__ __align__(16) float g_V     [6 * VSZ];
__device__ __align__(16) float g_als   [6 * AS];
__device__ __align__(16) float g_ald   [6 * AS];
__device__ __align__(16) float g_m     [6 * AS];
__device__ __align__(16) float g_den   [6 * AS];
__device__ __align__(16) float g_ex    [2600000];
__device__ __align__(16) float g_s1    [NS * HC];
__device__ __align__(16) float g_w1    [NW * HC];
__device__ __align__(16) float g_d1    [ND * HC];
__device__ __align__(16) float g_s2    [NS * HC];
__device__ __align__(16) float g_ptmp  [NS * PROJ_H];

// ---------------------------------------------------------------------------
// metadata struct (passed by value)
// ---------------------------------------------------------------------------
struct ConvMeta {
    const int*   ei[6];      // stacked [2,E] edge arrays
    const float* fptr[6];    // per-slot transformed feature base
    float*       out[6];     // scatter accumulators
    int fstride[6];
    int E[6];
    int cumEH[7];
    int cumE[7];
    int srcRows[6];
    int nt, H, C;
};

struct B8 { const float* p[8]; };

// ---------------------------------------------------------------------------
// TF32 tensor-core GEMM v4: BK=32, 3-stage cp.async pipeline, dynamic smem.
// One __syncthreads + one wait_group(1) per 32 K-steps (64 MMAs per warp
// between barriers; two tiles of copy in flight).
// 128x128 block tile, 256 threads (8 warps), warp tile 64x32,
// mma.sync.aligned.m16n8k8.row.col.f32.tf32.tf32.f32.
// ---------------------------------------------------------------------------
#define TBK 32
#define APAD 36
#define BPAD 132
#define NSTG 3
#define SM_A_FLOATS (NSTG * 128 * APAD)
#define SM_B_FLOATS (NSTG * TBK * BPAD)
#define TGEMM_SMEM ((SM_A_FLOATS + SM_B_FLOATS) * 4)

__device__ __forceinline__ uint32_t f2tf(float x)
{
    uint32_t r;
    asm("cvt.rna.tf32.f32 %0, %1;" : "=r"(r) : "f"(x));
    return r;
}

__device__ __forceinline__ void mma_tf32(float* c, const uint32_t* a, const uint32_t* b)
{
    asm volatile(
        "mma.sync.aligned.m16n8k8.row.col.f32.tf32.tf32.f32 "
        "{%0,%1,%2,%3}, {%4,%5,%6,%7}, {%8,%9}, {%0,%1,%2,%3};"
        : "+f"(c[0]), "+f"(c[1]), "+f"(c[2]), "+f"(c[3])
        : "r"(a[0]), "r"(a[1]), "r"(a[2]), "r"(a[3]), "r"(b[0]), "r"(b[1]));
}

__device__ __forceinline__ void cp16(uint32_t saddr, const void* gptr, int bytes)
{
    asm volatile("cp.async.cg.shared.global [%0], [%1], 16, %2;"
                 :: "r"(saddr), "l"(gptr), "r"(bytes));
}

__global__ __launch_bounds__(256, 2)
void tgemm(const float* __restrict__ A, B8 bp, const float* __restrict__ bias,
           float* __restrict__ C, int M, int K, int bstride, int ldc, int relu)
{
    extern __shared__ __align__(16) float dsm[];
    float* Asm = dsm;                  // [NSTG][128][APAD]
    float* Bsm = dsm + SM_A_FLOATS;    // [NSTG][TBK][BPAD]

    int tid = threadIdx.x;
    int row0 = blockIdx.y * 128;
    int col0 = blockIdx.x * 128;
    const float* B = bp.p[blockIdx.x];

    int lane = tid & 31, warp = tid >> 5;
    int g = lane >> 2, t = lane & 3;
    int wr = warp & 1, wc = warp >> 1;   // 2 warp-rows x 4 warp-cols

    float acc[4][4][4] = {};             // [mt][nt][4]

    // load indices: 4 cp16 per thread each for A (128x32) and B (32x128)
    int a_r[4], a_c[4], b_r[4], b_c[4];
#pragma unroll
    for (int i = 0; i < 4; i++) {
        int idx = tid + i * 256;
        a_r[i] = idx >> 3;          // 0..127
        a_c[i] = (idx & 7) * 4;     // 0..28
        b_r[i] = idx >> 5;          // 0..31
        b_c[i] = (idx & 31) * 4;    // 0..124
    }
    uint32_t sa0 = (uint32_t)__cvta_generic_to_shared(Asm);
    uint32_t sb0 = (uint32_t)__cvta_generic_to_shared(Bsm);

    const float* Aptr = A + (size_t)row0 * K;
    int a_ok[4];
#pragma unroll
    for (int i = 0; i < 4; i++) a_ok[i] = (row0 + a_r[i] < M) ? 16 : 0;

    int ntile = K / TBK;   // >= 4 for all calls

    // prologue: issue tiles 0 and 1
#pragma unroll
    for (int s = 0; s < 2; s++) {
        int k0 = s * TBK;
#pragma unroll
        for (int i = 0; i < 4; i++) {
            cp16(sa0 + ((s * 128 + a_r[i]) * APAD + a_c[i]) * 4,
                 Aptr + (size_t)a_r[i] * K + k0 + a_c[i], a_ok[i]);
            cp16(sb0 + ((s * TBK + b_r[i]) * BPAD + b_c[i]) * 4,
                 B + (size_t)(k0 + b_r[i]) * bstride + b_c[i], 16);
        }
        asm volatile("cp.async.commit_group;");
    }

    for (int kt = 0; kt < ntile; kt++) {
        asm volatile("cp.async.wait_group 1;");   // tile kt arrived
        __syncthreads();
        // issue tile kt+2 into stage (kt+2)%3 (freed by last iteration's sync)
        {
            int kn = kt + 2;
            if (kn < ntile) {
                int s = kn % NSTG;
                int k0 = kn * TBK;
#pragma unroll
                for (int i = 0; i < 4; i++) {
                    cp16(sa0 + ((s * 128 + a_r[i]) * APAD + a_c[i]) * 4,
                         Aptr + (size_t)a_r[i] * K + k0 + a_c[i], a_ok[i]);
                    cp16(sb0 + ((s * TBK + b_r[i]) * BPAD + b_c[i]) * 4,
                         B + (size_t)(k0 + b_r[i]) * bstride + b_c[i], 16);
                }
            }
            asm volatile("cp.async.commit_group;");
        }
        int s = kt % NSTG;
        const float* As = Asm + s * 128 * APAD;
        const float* Bs = Bsm + s * TBK * BPAD;
#pragma unroll
        for (int ks = 0; ks < 4; ks++) {
            int kb = ks * 8;
            uint32_t af[4][4], bf[4][2];
#pragma unroll
            for (int mt = 0; mt < 4; mt++) {
                int r = wr * 64 + mt * 16 + g;
                af[mt][0] = f2tf(As[r * APAD + kb + t]);
                af[mt][1] = f2tf(As[(r + 8) * APAD + kb + t]);
                af[mt][2] = f2tf(As[r * APAD + kb + t + 4]);
                af[mt][3] = f2tf(As[(r + 8) * APAD + kb + t + 4]);
            }
#pragma unroll
            for (int nt4 = 0; nt4 < 4; nt4++) {
                int c = wc * 32 + nt4 * 8 + g;
                bf[nt4][0] = f2tf(Bs[(kb + t) * BPAD + c]);
                bf[nt4][1] = f2tf(Bs[(kb + t + 4) * BPAD + c]);
            }
#pragma unroll
            for (int mt = 0; mt < 4; mt++)
#pragma unroll
                for (int nt4 = 0; nt4 < 4; nt4++)
                    mma_tf32(acc[mt][nt4], af[mt], bf[nt4]);
        }
    }

    // epilogue
#pragma unroll
    for (int mt = 0; mt < 4; mt++) {
        int m0 = row0 + wr * 64 + mt * 16 + g;
#pragma unroll
        for (int nt4 = 0; nt4 < 4; nt4++) {
            int cg = col0 + wc * 32 + nt4 * 8 + 2 * t;
            float b0 = bias ? bias[cg] : 0.f;
            float b1 = bias ? bias[cg + 1] : 0.f;
            if (m0 < M) {
                float v0 = acc[mt][nt4][0] + b0;
                float v1 = acc[mt][nt4][1] + b1;
                if (relu) { v0 = fmaxf(v0, 0.f); v1 = fmaxf(v1, 0.f); }
                float* p = C + (size_t)m0 * ldc + cg;
                p[0] = v0; p[1] = v1;
            }
            if (m0 + 8 < M) {
                float v0 = acc[mt][nt4][2] + b0;
                float v1 = acc[mt][nt4][3] + b1;
                if (relu) { v0 = fmaxf(v0, 0.f); v1 = fmaxf(v1, 0.f); }
                float* p = C + (size_t)(m0 + 8) * ldc + cg;
                p[0] = v0; p[1] = v1;
            }
        }
    }
}

// ---------------------------------------------------------------------------
// build dst-side attention vectors V[slot][k][h] = sum_c Wd[t,k,h*C+c]*ad[t,h,c]
// ---------------------------------------------------------------------------
__global__ void build_vd_all(const float* __restrict__ Wd, const float* __restrict__ ad,
                             float* __restrict__ Vall, int K, int H, int C,
                             int4 tmap)
{
    int slot_t[4] = { tmap.x, tmap.y, tmap.z, tmap.w };
    int slot = blockIdx.y;
    int typ = slot_t[slot & 3];
    if (slot >= 4) typ = (slot == 4) ? 4 : 5;   // conv1 slots 4,5 map to types 4,5
    int idx = blockIdx.x * blockDim.x + threadIdx.x;
    if (idx >= K * H) return;
    int k = idx / H, h = idx - (idx / H) * H;
    const float* w = Wd + (size_t)typ * K * HC + (size_t)k * HC + h * C;
    const float* av = ad + typ * HC + h * C;
    float s = 0.f;
    for (int c = 0; c < C; c++) s += w[c] * av[c];
    Vall[slot * VSZ + k * H + h] = s;
}

// ---------------------------------------------------------------------------
// als[slot][row][h] = sum_c feat[row, h*C+c] * a_s[t, h*C+c]  (warp per (row,h))
// ---------------------------------------------------------------------------
__global__ void als_feat_all(const float* __restrict__ a_s,
                             float* __restrict__ als_all, ConvMeta md, int4 tmap01, int2 tmap2)
{
    int slot = blockIdx.y;
    int typ;
    {
        int tm[6] = { tmap01.x, tmap01.y, tmap01.z, tmap01.w, tmap2.x, tmap2.y };
        typ = tm[slot];
    }
    int id = (blockIdx.x * blockDim.x + threadIdx.x) >> 5;
    int lane = threadIdx.x & 31;
    int H = md.H, C = md.C;
    int rows = md.srcRows[slot];
    if (id >= rows * H) return;
    int row = id / H, h = id - (id / H) * H;
    const float* f = md.fptr[slot] + (size_t)row * md.fstride[slot] + h * C;
    const float* a = a_s + typ * HC + h * C;
    float s = 0.f;
    for (int c = lane; c < C; c += 32) s += f[c] * a[c];
#pragma unroll
    for (int o = 16; o > 0; o >>= 1) s += __shfl_xor_sync(0xffffffffu, s, o);
    if (lane == 0) als_all[slot * AS + row * H + h] = s;
}

// ---------------------------------------------------------------------------
// Grouped ald GEMV: up to 4 slots sharing the same dstX, warp per row.
// ---------------------------------------------------------------------------
__global__ void gemv_ald_group(const float* __restrict__ X, int rows, int K, int H,
                               int4 slots, int ns,
                               const float* __restrict__ Vall, float* __restrict__ ald_all)
{
    int warp = (blockIdx.x * blockDim.x + threadIdx.x) >> 5;
    int lane = threadIdx.x & 31;
    if (warp >= rows) return;
    int sl[4] = { slots.x, slots.y, slots.z, slots.w };
    const float* x = X + (size_t)warp * K;
    float acc[16];
#pragma unroll
    for (int i = 0; i < 16; i++) acc[i] = 0.f;
    for (int k = lane; k < K; k += 32) {
        float xv = x[k];
#pragma unroll
        for (int si = 0; si < 4; si++) {
            if (si >= ns) break;
            const float* v = Vall + sl[si] * VSZ + k * H;
#pragma unroll
            for (int h = 0; h < 4; h++) {
                if (h >= H) break;
                acc[si * 4 + h] += xv * v[h];
            }
        }
    }
#pragma unroll
    for (int i = 0; i < 16; i++)
#pragma unroll
        for (int o = 16; o > 0; o >>= 1)
            acc[i] += __shfl_xor_sync(0xffffffffu, acc[i], o);
    if (lane == 0) {
        for (int si = 0; si < ns; si++)
            for (int h = 0; h < H; h++)
                ald_all[sl[si] * AS + warp * H + h] = acc[si * 4 + h];
    }
}

// ---------------------------------------------------------------------------
// misc
// ---------------------------------------------------------------------------
__global__ void fill_md_kernel(float* __restrict__ m, float* __restrict__ den, int n)
{
    int i = blockIdx.x * blockDim.x + threadIdx.x;
    for (; i < n; i += gridDim.x * blockDim.x) { m[i] = -INFINITY; den[i] = 0.f; }
}

__global__ void init_bias_kernel(float* __restrict__ out, const float* __restrict__ b,
                                 int4 ts, int total)
{
    int i = blockIdx.x * blockDim.x + threadIdx.x;
    for (; i < total; i += gridDim.x * blockDim.x) {
        int c = i & (HC - 1);
        float v = b[ts.x * HC + c];
        if (ts.y >= 0) v += b[ts.y * HC + c];
        if (ts.z >= 0) v += b[ts.z * HC + c];
        if (ts.w >= 0) v += b[ts.w * HC + c];
        out[i] = v;
    }
}

__device__ __forceinline__ void atomicMaxFloat(float* addr, float val)
{
    if (val >= 0.f) atomicMax((int*)addr, __float_as_int(val));
    else            atomicMin((unsigned int*)addr, __float_as_uint(val));
}

// ---------------------------------------------------------------------------
// edge pipeline (batched over all slots)
// ---------------------------------------------------------------------------
__global__ void edge_pass1_all(const float* __restrict__ als_all, const float* __restrict__ ald_all,
                               float* __restrict__ m_all, ConvMeta md)
{
    int idx = blockIdx.x * blockDim.x + threadIdx.x;
    if (idx >= md.cumEH[md.nt]) return;
    int slot = 0;
    while (idx >= md.cumEH[slot + 1]) slot++;
    int local = idx - md.cumEH[slot];
    int H = md.H;
    int e, h;
    if (H == 4) { e = local >> 2; h = local & 3; } else { e = local; h = 0; }
    const int* ei = md.ei[slot];
    int s = ei[e], d = ei[md.E[slot] + e];
    float v = als_all[slot * AS + s * H + h] + ald_all[slot * AS + d * H + h];
    v = (v > 0.f) ? v : 0.2f * v;
    atomicMaxFloat(&m_all[slot * AS + d * H + h], v);
}

__global__ void edge_pass2_all(const float* __restrict__ als_all, const float* __restrict__ ald_all,
                               const float* __restrict__ m_all,
                               float* __restrict__ exbuf, float* __restrict__ den_all, ConvMeta md)
{
    int idx = blockIdx.x * blockDim.x + threadIdx.x;
    if (idx >= md.cumEH[md.nt]) return;
    int slot = 0;
    while (idx >= md.cumEH[slot + 1]) slot++;
    int local = idx - md.cumEH[slot];
    int H = md.H;
    int e, h;
    if (H == 4) { e = local >> 2; h = local & 3; } else { e = local; h = 0; }
    const int* ei = md.ei[slot];
    int s = ei[e], d = ei[md.E[slot] + e];
    float v = als_all[slot * AS + s * H + h] + ald_all[slot * AS + d * H + h];
    v = (v > 0.f) ? v : 0.2f * v;
    float ex = __expf(v - m_all[slot * AS + d * H + h]);
    exbuf[idx] = ex;
    atomicAdd(&den_all[slot * AS + d * H + h], ex);
}

__device__ __forceinline__ void red_add_v4(float* p, float a, float b, float c, float d)
{
    asm volatile("red.global.add.v4.f32 [%0], {%1,%2,%3,%4};"
                 :: "l"(p), "f"(a), "f"(b), "f"(c), "f"(d) : "memory");
}

__global__ void edge_scatter_all(const float* __restrict__ exbuf, const float* __restrict__ den_all,
                                 ConvMeta md)
{
    int wf = (blockIdx.x * blockDim.x + threadIdx.x) >> 5;
    if (wf >= md.cumE[md.nt]) return;
    int lane = threadIdx.x & 31;
    int slot = 0;
    while (wf >= md.cumE[slot + 1]) slot++;
    int e = wf - md.cumE[slot];
    int H = md.H;
    const int* ei = md.ei[slot];
    int s = ei[e], d = ei[md.E[slot] + e];
    const float4* fs = (const float4*)(md.fptr[slot] + (size_t)s * md.fstride[slot]);
    float* od = md.out[slot] + (size_t)d * HC;
    int ebase = md.cumEH[slot] + e * H;
    const float* dslot = den_all + slot * AS + d * H;
#pragma unroll
    for (int j = 0; j < 2; j++) {
        int i4 = lane + j * 32;
        int base = i4 * 4;
        int h = (H == 4) ? (base >> 6) : 0;
        float alpha = exbuf[ebase + h] / (dslot[h] + 1e-16f);
        float4 v = fs[i4];
        red_add_v4(&od[base], v.x * alpha, v.y * alpha, v.z * alpha, v.w * alpha);
    }
}

// ---------------------------------------------------------------------------
// (optional relu) + LayerNorm over last dim D=256, one 256-thread block per row
// ---------------------------------------------------------------------------
__global__ void relu_ln_kernel(const float* __restrict__ in, float* __restrict__ out, int pre_relu)
{
    int n = blockIdx.x;
    int t = threadIdx.x;
    int lane = t & 31, w = t >> 5;
    float v = in[(size_t)n * HC + t];
    if (pre_relu) v = fmaxf(v, 0.f);
    __shared__ float ws[8];
    float s = v;
#pragma unroll
    for (int o = 16; o > 0; o >>= 1) s += __shfl_xor_sync(0xffffffffu, s, o);
    if (lane == 0) ws[w] = s;
    __syncthreads();
    float mu = 0.f;
#pragma unroll
    for (int i = 0; i < 8; i++) mu += ws[i];
    mu *= (1.f / HC);
    __syncthreads();
    float dv = v - mu;
    s = dv * dv;
#pragma unroll
    for (int o = 16; o > 0; o >>= 1) s += __shfl_xor_sync(0xffffffffu, s, o);
    if (lane == 0) ws[w] = s;
    __syncthreads();
    float var = 0.f;
#pragma unroll
    for (int i = 0; i < 8; i++) var += ws[i];
    var *= (1.f / HC);
    out[(size_t)n * HC + t] = dv * rsqrtf(var + 1e-5f);
}

// ---------------------------------------------------------------------------
// host orchestration
// ---------------------------------------------------------------------------
static inline void launch_tgemm(const float* A, const float* B, const float* bias, float* C,
                                int M, int N, int K, int relu)
{
    B8 bp = {};
    int gx = N / 128;
    for (int i = 0; i < gx; i++) bp.p[i] = B + i * 128;
    dim3 grid(gx, (M + 127) / 128);
    tgemm<<<grid, 256, TGEMM_SMEM>>>(A, bp, bias, C, M, K, N, N, relu);
}

extern "C" void kernel_launch(void* const* d_in, const int* in_sizes, int n_in,
                              void* d_out, int out_size)
{
    cudaFuncSetAttribute(tgemm, cudaFuncAttributeMaxDynamicSharedMemorySize, TGEMM_SMEM);

    const float* x_sent = (const float*)d_in[0];
    const float* x_word = (const float*)d_in[1];
    const float* x_doc  = (const float*)d_in[2];
    const int*   ei[6]  = { (const int*)d_in[3], (const int*)d_in[4], (const int*)d_in[5],
                            (const int*)d_in[6], (const int*)d_in[7], (const int*)d_in[8] };
    int Ecnt[6];
    for (int t = 0; t < 6; t++) Ecnt[t] = in_sizes[3 + t] / 2;
    const float* Wls = (const float*)d_in[9];
    const float* bls = (const float*)d_in[10];
    const float* Wlw = (const float*)d_in[11];
    const float* blw = (const float*)d_in[12];
    const float* Wld = (const float*)d_in[13];
    const float* bld = (const float*)d_in[14];
    const float* W1s = (const float*)d_in[15];
    const float* W1d = (const float*)d_in[16];
    const float* a1s = (const float*)d_in[17];
    const float* a1d = (const float*)d_in[18];
    const float* b1  = (const float*)d_in[19];
    const float* W2s = (const float*)d_in[20];
    const float* W2d = (const float*)d_in[21];
    const float* a2s = (const float*)d_in[22];
    const float* a2d = (const float*)d_in[23];
    const float* b2  = (const float*)d_in[24];
    const float* Wp1 = (const float*)d_in[25];
    const float* bp1 = (const float*)d_in[26];
    const float* Wp2 = (const float*)d_in[27];
    const float* bp2 = (const float*)d_in[28];

    float *h_sent, *h_word, *h_doc, *feat, *Vall, *als, *ald, *m, *den, *exbuf;
    float *s1, *w1, *d1, *s2, *ptmp;
    cudaGetSymbolAddress((void**)&h_sent, g_h_sent);
    cudaGetSymbolAddress((void**)&h_word, g_h_word);
    cudaGetSymbolAddress((void**)&h_doc,  g_h_doc);
    cudaGetSymbolAddress((void**)&feat,   g_feat);
    cudaGetSymbolAddress((void**)&Vall,   g_V);
    cudaGetSymbolAddress((void**)&als,    g_als);
    cudaGetSymbolAddress((void**)&ald,    g_ald);
    cudaGetSymbolAddress((void**)&m,      g_m);
    cudaGetSymbolAddress((void**)&den,    g_den);
    cudaGetSymbolAddress((void**)&exbuf,  g_ex);
    cudaGetSymbolAddress((void**)&s1,     g_s1);
    cudaGetSymbolAddress((void**)&w1,     g_w1);
    cudaGetSymbolAddress((void**)&d1,     g_d1);
    cudaGetSymbolAddress((void**)&s2,     g_s2);
    cudaGetSymbolAddress((void**)&ptmp,   g_ptmp);

    float* out_s2  = (float*)d_out;
    float* out_prj = out_s2 + (size_t)NS * HC;

    // feat sub-buffers
    float* featS = feat;
    float* featW = feat + (size_t)NS * 1024;
    float* featD = featW + (size_t)NW * 256;
    float* featS2 = feat;
    float* featW2 = feat + (size_t)NS * 512;
    float* featD2 = featW2 + (size_t)NW * 256;

    // ---- stage A: input linears + relu ----
    launch_tgemm(x_sent, Wls, bls, h_sent, NS, DIN, DIN, 1);
    launch_tgemm(x_word, Wlw, blw, h_word, NW, DIN, DIN, 1);
    launch_tgemm(x_doc,  Wld, bld, h_doc,  ND, DIN, DIN, 1);

    // ---- conv1 feat GEMMs ----
    {
        B8 bp = {};
        const int st[4] = { 0, 1, 3, 5 };
        for (int i = 0; i < 8; i++)
            bp.p[i] = W1s + (size_t)st[i >> 1] * DIN * HC + (i & 1) * 128;
        tgemm<<<dim3(8, (NS + 127) / 128), 256, TGEMM_SMEM>>>(h_sent, bp, nullptr, featS, NS, DIN, HC, 1024, 0);
        launch_tgemm(h_word, W1s + 2 * (size_t)DIN * HC, nullptr, featW, NW, HC, DIN, 0);
        launch_tgemm(h_doc,  W1s + 4 * (size_t)DIN * HC, nullptr, featD, ND, HC, DIN, 0);
    }

    // ---- conv1 metadata ----
    ConvMeta m1 = {};
    {
        int          Nsrc1[6] = { NS, NS, NW, NS, ND, NS };
        float*       acc1[6]  = { s1, s1, s1, w1, s1, d1 };
        const float* fp1[6]   = { featS + 0, featS + 256, featW, featS + 512, featD, featS + 768 };
        int          fs1[6]   = { 1024, 1024, 256, 1024, 256, 1024 };
        m1.nt = 6; m1.H = 4; m1.C = 64;
        m1.cumEH[0] = 0; m1.cumE[0] = 0;
        for (int t = 0; t < 6; t++) {
            m1.ei[t] = ei[t];
            m1.fptr[t] = fp1[t];
            m1.fstride[t] = fs1[t];
            m1.out[t] = acc1[t];
            m1.E[t] = Ecnt[t];
            m1.cumEH[t + 1] = m1.cumEH[t] + Ecnt[t] * 4;
            m1.cumE[t + 1] = m1.cumE[t] + Ecnt[t];
            m1.srcRows[t] = Nsrc1[t];
        }
    }

    init_bias_kernel<<<4096, 256>>>(s1, b1, make_int4(0, 1, 2, 4), NS * HC);
    init_bias_kernel<<<4096, 256>>>(w1, b1, make_int4(3, -1, -1, -1), NW * HC);
    init_bias_kernel<<<256,  256>>>(d1, b1, make_int4(5, -1, -1, -1), ND * HC);

    // attention values (fp32)
    build_vd_all<<<dim3((DIN * 4 + 127) / 128, 6), 128>>>(W1d, a1d, Vall, DIN, 4, 64,
                                                          make_int4(0, 1, 2, 3));
    als_feat_all<<<dim3((NW * 4 + 7) / 8, 6), 256>>>(a1s, als, m1,
                                                     make_int4(0, 1, 2, 3), make_int2(4, 5));
    gemv_ald_group<<<(NS * 32 + 255) / 256, 256>>>(h_sent, NS, DIN, 4, make_int4(0, 1, 2, 4), 4, Vall, ald);
    gemv_ald_group<<<(NW * 32 + 255) / 256, 256>>>(h_word, NW, DIN, 4, make_int4(3, 0, 0, 0), 1, Vall, ald);
    gemv_ald_group<<<(ND * 32 + 255) / 256, 256>>>(h_doc,  ND, DIN, 4, make_int4(5, 0, 0, 0), 1, Vall, ald);

    fill_md_kernel<<<2048, 256>>>(m, den, 6 * AS);
    {
        int tot = m1.cumEH[6];
        edge_pass1_all<<<(tot + 255) / 256, 256>>>(als, ald, m, m1);
        edge_pass2_all<<<(tot + 255) / 256, 256>>>(als, ald, m, exbuf, den, m1);
        int totw = m1.cumE[6];
        edge_scatter_all<<<(totw * 32 + 255) / 256, 256>>>(exbuf, den, m1);
    }

    // ---- relu + LN ----
    relu_ln_kernel<<<NS, HC>>>(s1, s1, 1);
    relu_ln_kernel<<<NW, HC>>>(w1, w1, 1);
    relu_ln_kernel<<<ND, HC>>>(d1, d1, 1);

    // ---- conv2 feat GEMMs ----
    {
        B8 bp = {};
        const int st[2] = { 0, 1 };
        for (int i = 0; i < 4; i++)
            bp.p[i] = W2s + (size_t)st[i >> 1] * HC * HC + (i & 1) * 128;
        tgemm<<<dim3(4, (NS + 127) / 128), 256, TGEMM_SMEM>>>(s1, bp, nullptr, featS2, NS, HC, HC, 512, 0);
        launch_tgemm(w1, W2s + 2 * (size_t)HC * HC, nullptr, featW2, NW, HC, HC, 0);
        launch_tgemm(d1, W2s + 4 * (size_t)HC * HC, nullptr, featD2, ND, HC, HC, 0);
    }

    // ---- conv2 metadata (types {0,1,2,4} -> sentences) ----
    ConvMeta m2 = {};
    {
        const int    t2[4]    = { 0, 1, 2, 4 };
        int          Nsrc2[4] = { NS, NS, NW, ND };
        const float* fp2[4]   = { featS2 + 0, featS2 + 256, featW2, featD2 };
        int          fs2[4]   = { 512, 512, 256, 256 };
        m2.nt = 4; m2.H = 1; m2.C = 256;
        m2.cumEH[0] = 0; m2.cumE[0] = 0;
        for (int i = 0; i < 4; i++) {
            m2.ei[i] = ei[t2[i]];
            m2.fptr[i] = fp2[i];
            m2.fstride[i] = fs2[i];
            m2.out[i] = s2;
            m2.E[i] = Ecnt[t2[i]];
            m2.cumEH[i + 1] = m2.cumEH[i] + Ecnt[t2[i]];
            m2.cumE[i + 1] = m2.cumE[i] + Ecnt[t2[i]];
            m2.srcRows[i] = Nsrc2[i];
        }
    }

    init_bias_kernel<<<4096, 256>>>(s2, b2, make_int4(0, 1, 2, 4), NS * HC);

    build_vd_all<<<dim3((HC * 1 + 127) / 128, 4), 128>>>(W2d, a2d, Vall, HC, 1, 256,
                                                         make_int4(0, 1, 2, 4));
    als_feat_all<<<dim3((NW * 1 + 7) / 8, 4), 256>>>(a2s, als, m2,
                                                     make_int4(0, 1, 2, 4), make_int2(0, 0));
    gemv_ald_group<<<(NS * 32 + 255) / 256, 256>>>(s1, NS, HC, 1, make_int4(0, 1, 2, 3), 4, Vall, ald);

    fill_md_kernel<<<2048, 256>>>(m, den, 6 * AS);
    {
        int tot = m2.cumEH[4];
        edge_pass1_all<<<(tot + 255) / 256, 256>>>(als, ald, m, m2);
        edge_pass2_all<<<(tot + 255) / 256, 256>>>(als, ald, m, exbuf, den, m2);
        int totw = m2.cumE[4];
        edge_scatter_all<<<(totw * 32 + 255) / 256, 256>>>(exbuf, den, m2);
    }

    // ---- final LN (no relu) -> output s2 ----
    relu_ln_kernel<<<NS, HC>>>(s2, out_s2, 0);

    // ---- projection head ----
    if (out_size >= NS * (HC + PROJ_H)) {
        launch_tgemm(out_s2, Wp1, bp1, ptmp, NS, PROJ_H, HC, 1);
        launch_tgemm(ptmp, Wp2, bp2, out_prj, NS, PROJ_H, PROJ_H, 0);
    }
}